// round 5
// baseline (speedup 1.0000x reference)
#include <cuda_runtime.h>
#include <math.h>

#define NV   100000
#define NE   10000
#define NP   1600000
#define CIN  256
#define CMID 128
#define COUT 64
#define NEG  0.2f

// ---------------- scratch (device globals; no allocation allowed) ----------
__device__ float g_h[NV * COUT];        // MLP output h
__device__ float g_efeat[NE * COUT];    // hyperedge mean feature
__device__ int   g_cnt_e[NE];           // hyperedge degree
__device__ int   g_cnt_v[NV];           // vertex incidence degree
__device__ int   g_cnt_g[NV];           // vertex graph in-degree
__device__ int   g_cur_e[NE];           // fill cursors (start at offset)
__device__ int   g_cur_v[NV];
__device__ int   g_cur_g[NV];
__device__ int   g_off_e[NE];
__device__ int   g_off_v[NV];
__device__ int   g_off_g[NV];
__device__ int   g_csr_ev[NP];          // per-hyperedge: vertex ids
__device__ int   g_csr_ve[NP];          // per-vertex: hyperedge ids
__device__ int   g_csr_g[NP];           // per-vertex: src vertex ids

__device__ __forceinline__ float lrelu(float v) { return v > 0.f ? v : NEG * v; }

typedef unsigned long long u64;

__device__ __forceinline__ u64 fma2(u64 a, u64 b, u64 c) {
    u64 d;
    asm("fma.rn.f32x2 %0, %1, %2, %3;" : "=l"(d) : "l"(a), "l"(b), "l"(c));
    return d;
}
__device__ __forceinline__ float sum2(u64 p) {
    float lo, hi;
    asm("mov.b64 {%0,%1}, %2;" : "=f"(lo), "=f"(hi) : "l"(p));
    return lo + hi;
}

// ---------------- zero counters ---------------------------------------------
__global__ void zero_kernel() {
    int i = blockIdx.x * blockDim.x + threadIdx.x;
    if (i < NE) g_cnt_e[i] = 0;
    if (i < NV) { g_cnt_v[i] = 0; g_cnt_g[i] = 0; }
}

// ---------------- histogram -------------------------------------------------
__global__ void count_kernel(const int* __restrict__ hg_v,
                             const int* __restrict__ hg_e,
                             const int* __restrict__ g_dst) {
    int i = blockIdx.x * blockDim.x + threadIdx.x;
    if (i >= NP) return;
    atomicAdd(&g_cnt_e[__ldg(hg_e + i)], 1);
    atomicAdd(&g_cnt_v[__ldg(hg_v + i)], 1);
    atomicAdd(&g_cnt_g[__ldg(g_dst + i)], 1);
}

// ---------------- 3 exclusive scans (one block each); cur := off -----------
#define SCAN_T 1024
__global__ void scan_kernel() {
    const int* cnt; int* off; int* cur; int n;
    if (blockIdx.x == 0)      { cnt = g_cnt_e; off = g_off_e; cur = g_cur_e; n = NE; }
    else if (blockIdx.x == 1) { cnt = g_cnt_v; off = g_off_v; cur = g_cur_v; n = NV; }
    else                      { cnt = g_cnt_g; off = g_off_g; cur = g_cur_g; n = NV; }

    __shared__ int ssum[SCAN_T];
    int t = threadIdx.x;
    int chunk = (n + SCAN_T - 1) / SCAN_T;
    int lo = t * chunk, hi = min(n, lo + chunk);
    int s = 0;
    for (int i = lo; i < hi; i++) s += cnt[i];
    ssum[t] = s;
    __syncthreads();
    for (int d = 1; d < SCAN_T; d <<= 1) {
        int v = (t >= d) ? ssum[t - d] : 0;
        __syncthreads();
        ssum[t] += v;
        __syncthreads();
    }
    int excl = (t == 0) ? 0 : ssum[t - 1];
    for (int i = lo; i < hi; i++) {
        off[i] = excl; cur[i] = excl;
        excl += cnt[i];
    }
}

// ---------------- CSR fill (cursor holds absolute slot) ---------------------
__global__ void fill_kernel(const int* __restrict__ hg_v,
                            const int* __restrict__ hg_e,
                            const int* __restrict__ g_src,
                            const int* __restrict__ g_dst) {
    int i = blockIdx.x * blockDim.x + threadIdx.x;
    if (i >= NP) return;
    int e = __ldg(hg_e + i), v = __ldg(hg_v + i);
    g_csr_ev[atomicAdd(&g_cur_e[e], 1)] = v;
    g_csr_ve[atomicAdd(&g_cur_v[v], 1)] = e;
    int d = __ldg(g_dst + i);
    g_csr_g[atomicAdd(&g_cur_g[d], 1)] = __ldg(g_src + i);
}

// ---------------- fused MLP: h = lrelu(x@W1+b1)@W2 + b2 --------------------
#define TILE_R 32
#define RPW    4
#define MLP_THREADS 256
#define S1 (CIN + 2)
#define S2 (CMID + 2)
#define SMEM_FLOATS (CMID*S1 + COUT*S2 + TILE_R*CIN + TILE_R*CMID + CMID + COUT)

__global__ __launch_bounds__(MLP_THREADS, 1)
void mlp_kernel(const float* __restrict__ x,
                const float* __restrict__ W1, const float* __restrict__ b1,
                const float* __restrict__ W2, const float* __restrict__ b2) {
    extern __shared__ float sm[];
    float* W1T  = sm;
    float* W2T  = W1T + CMID * S1;
    float* xs   = W2T + COUT * S2;
    float* mids = xs  + TILE_R * CIN;
    float* b1s  = mids + TILE_R * CMID;
    float* b2s  = b1s + CMID;

    int tid = threadIdx.x;
    for (int i = tid; i < CIN * CMID; i += MLP_THREADS) {
        int k = i >> 7, j = i & 127;
        W1T[j * S1 + k] = W1[i];
    }
    for (int i = tid; i < CMID * COUT; i += MLP_THREADS) {
        int k = i >> 6, j = i & 63;
        W2T[j * S2 + k] = W2[i];
    }
    if (tid < CMID) b1s[tid] = b1[tid];
    if (tid < COUT) b2s[tid] = b2[tid];

    int warp = tid >> 5, lane = tid & 31;
    int ntiles = NV / TILE_R;

    for (int tile = blockIdx.x; tile < ntiles; tile += gridDim.x) {
        __syncthreads();
        int row0 = tile * TILE_R;
        for (int i = tid; i < TILE_R * CIN / 4; i += MLP_THREADS)
            ((float4*)xs)[i] = ((const float4*)(x + (size_t)row0 * CIN))[i];
        __syncthreads();

        u64 acc[RPW][4];
#pragma unroll
        for (int r = 0; r < RPW; r++)
#pragma unroll
            for (int jj = 0; jj < 4; jj++) acc[r][jj] = 0ull;

        const float* xrow = xs + (warp * RPW) * CIN;
        const float* wbase = W1T + lane * S1;
#pragma unroll 4
        for (int k = 0; k < CIN; k += 2) {
            u64 xv[RPW], wv[4];
#pragma unroll
            for (int r = 0; r < RPW; r++)
                xv[r] = *(const u64*)(xrow + r * CIN + k);
#pragma unroll
            for (int jj = 0; jj < 4; jj++)
                wv[jj] = *(const u64*)(wbase + (jj * 32) * S1 + k);
#pragma unroll
            for (int r = 0; r < RPW; r++)
#pragma unroll
                for (int jj = 0; jj < 4; jj++)
                    acc[r][jj] = fma2(xv[r], wv[jj], acc[r][jj]);
        }
#pragma unroll
        for (int jj = 0; jj < 4; jj++) {
            int j = jj * 32 + lane;
            float b = b1s[j];
#pragma unroll
            for (int r = 0; r < RPW; r++)
                mids[(warp * RPW + r) * CMID + j] = lrelu(sum2(acc[r][jj]) + b);
        }
        __syncwarp();

        u64 acc2[RPW][2];
#pragma unroll
        for (int r = 0; r < RPW; r++) { acc2[r][0] = 0ull; acc2[r][1] = 0ull; }

        const float* mrow = mids + (warp * RPW) * CMID;
        const float* w2base = W2T + lane * S2;
#pragma unroll 4
        for (int k = 0; k < CMID; k += 2) {
            u64 mv[RPW], wv[2];
#pragma unroll
            for (int r = 0; r < RPW; r++)
                mv[r] = *(const u64*)(mrow + r * CMID + k);
#pragma unroll
            for (int jj = 0; jj < 2; jj++)
                wv[jj] = *(const u64*)(w2base + (jj * 32) * S2 + k);
#pragma unroll
            for (int r = 0; r < RPW; r++)
#pragma unroll
                for (int jj = 0; jj < 2; jj++)
                    acc2[r][jj] = fma2(mv[r], wv[jj], acc2[r][jj]);
        }
#pragma unroll
        for (int jj = 0; jj < 2; jj++) {
            int j = jj * 32 + lane;
            float b = b2s[j];
#pragma unroll
            for (int r = 0; r < RPW; r++)
                g_h[(size_t)(row0 + warp * RPW + r) * COUT + j] = sum2(acc2[r][jj]) + b;
        }
    }
}

// ---------------- generic 16-lane-per-row CSR mean gather -------------------
// Uniform index loads broadcast within the 16-lane group (no shfl); unrolled
// for MLP. acc16 helper accumulates one neighbor.
__device__ __forceinline__ void acc4(float4& a, const float* __restrict__ feat,
                                     int src, int t) {
    float4 v = __ldg((const float4*)(feat + (size_t)src * COUT) + t);
    a.x += v.x; a.y += v.y; a.z += v.z; a.w += v.w;
}

__device__ __forceinline__ float4 gather_mean(const float* __restrict__ feat,
                                              const int* __restrict__ csr,
                                              int base, int deg, int t) {
    float4 a0 = make_float4(0.f, 0.f, 0.f, 0.f);
    float4 a1 = make_float4(0.f, 0.f, 0.f, 0.f);
    float4 a2 = make_float4(0.f, 0.f, 0.f, 0.f);
    float4 a3 = make_float4(0.f, 0.f, 0.f, 0.f);
    const int* p = csr + base;
    int j = 0;
    for (; j + 4 <= deg; j += 4) {
        int s0 = __ldg(p + j + 0);
        int s1 = __ldg(p + j + 1);
        int s2 = __ldg(p + j + 2);
        int s3 = __ldg(p + j + 3);
        acc4(a0, feat, s0, t);
        acc4(a1, feat, s1, t);
        acc4(a2, feat, s2, t);
        acc4(a3, feat, s3, t);
    }
    for (; j < deg; j++) acc4(a0, feat, __ldg(p + j), t);
    float inv = 1.f / (float)max(deg, 1);
    float4 o;
    o.x = (a0.x + a1.x + a2.x + a3.x) * inv;
    o.y = (a0.y + a1.y + a2.y + a3.y) * inv;
    o.z = (a0.z + a1.z + a2.z + a3.z) * inv;
    o.w = (a0.w + a1.w + a2.w + a3.w) * inv;
    return o;
}

// ---------------- v2e gather: e_feat[e] = mean over vertices ----------------
__global__ void gather_e_kernel() {
    int gt = blockIdx.x * blockDim.x + threadIdx.x;
    int e = gt >> 4;
    if (e >= NE) return;
    int t = gt & 15;
    float4 o = gather_mean(g_h, g_csr_ev, g_off_e[e], g_cnt_e[e], t);
    ((float4*)(g_efeat + (size_t)e * COUT))[t] = o;
}

// ---------------- fused per-vertex: e2v gather + graph gather + epilogue ----
__global__ void vertex_kernel(const float* __restrict__ w,
                              float* __restrict__ out) {
    int gt = blockIdx.x * blockDim.x + threadIdx.x;
    int v = gt >> 4;
    if (v >= NV) return;
    int t = gt & 15;

    float4 xh = gather_mean(g_efeat, g_csr_ve, g_off_v[v], g_cnt_v[v], t);
    float4 xg = gather_mean(g_h,     g_csr_g,  g_off_g[v], g_cnt_g[v], t);

    float e0 = expf(w[0]), e1 = expf(w[1]);
    float sw0 = e0 / (e0 + e1), sw1 = e1 / (e0 + e1);
    float4 h = __ldg((const float4*)(g_h + (size_t)v * COUT) + t);
    float4 o;
    o.x = lrelu(sw0 * 0.5f * (xg.x + xh.x) + sw1 * h.x);
    o.y = lrelu(sw0 * 0.5f * (xg.y + xh.y) + sw1 * h.y);
    o.z = lrelu(sw0 * 0.5f * (xg.z + xh.z) + sw1 * h.z);
    o.w = lrelu(sw0 * 0.5f * (xg.w + xh.w) + sw1 * h.w);
    ((float4*)(out + (size_t)v * COUT))[t] = o;
}

// ---------------- launch ----------------------------------------------------
extern "C" void kernel_launch(void* const* d_in, const int* in_sizes, int n_in,
                              void* d_out, int out_size) {
    const float* x    = (const float*)d_in[0];
    const float* W1   = (const float*)d_in[1];
    const float* b1   = (const float*)d_in[2];
    const float* W2   = (const float*)d_in[3];
    const float* b2   = (const float*)d_in[4];
    const float* w    = (const float*)d_in[5];
    const int*   hg_v = (const int*)d_in[6];
    const int*   hg_e = (const int*)d_in[7];
    const int*   g_src= (const int*)d_in[8];
    const int*   g_dst= (const int*)d_in[9];
    float* out = (float*)d_out;

    const size_t smem_bytes = (size_t)SMEM_FLOATS * sizeof(float); // ~210KB
    cudaFuncSetAttribute(mlp_kernel, cudaFuncAttributeMaxDynamicSharedMemorySize,
                         (int)smem_bytes);

    // CSR build
    zero_kernel<<<(NV + 255) / 256, 256>>>();
    count_kernel<<<(NP + 255) / 256, 256>>>(hg_v, hg_e, g_dst);
    scan_kernel<<<3, SCAN_T>>>();
    fill_kernel<<<(NP + 255) / 256, 256>>>(hg_v, hg_e, g_src, g_dst);

    // MLP
    mlp_kernel<<<148, MLP_THREADS, smem_bytes>>>(x, W1, b1, W2, b2);

    // gathers
    gather_e_kernel<<<(NE * 16 + 255) / 256, 256>>>();
    vertex_kernel<<<(NV * 16 + 255) / 256, 256>>>(w, out);
}

// round 6
// speedup vs baseline: 1.0293x; 1.0293x over previous
#include <cuda_runtime.h>
#include <math.h>

#define NV   100000
#define NE   10000
#define NP   1600000
#define CIN  256
#define CMID 128
#define COUT 64
#define NEG  0.2f

// ---------------- scratch (device globals; no allocation allowed) ----------
__device__ float g_h[NV * COUT];        // MLP output h
__device__ float g_esum[NE * COUT];     // hyperedge accumulator
__device__ float g_ecnt[NE];            // hyperedge degree
__device__ float g_efeat[NE * COUT];    // hyperedge mean feature
__device__ float g_hgsum[NV * COUT];    // e2v accumulator
__device__ float g_gsum[NV * COUT];     // graph accumulator
__device__ float g_vcnt_hg[NV];         // vertex incidence degree
__device__ float g_vcnt_g[NV];          // vertex graph in-degree

__device__ __forceinline__ float lrelu(float v) { return v > 0.f ? v : NEG * v; }

typedef unsigned long long u64;

__device__ __forceinline__ u64 fma2(u64 a, u64 b, u64 c) {
    u64 d;
    asm("fma.rn.f32x2 %0, %1, %2, %3;" : "=l"(d) : "l"(a), "l"(b), "l"(c));
    return d;
}
__device__ __forceinline__ float sum2(u64 p) {
    float lo, hi;
    asm("mov.b64 {%0,%1}, %2;" : "=f"(lo), "=f"(hi) : "l"(p));
    return lo + hi;
}

// ---------------- zero accumulators ----------------------------------------
__global__ void zero_kernel() {
    int stride = gridDim.x * blockDim.x;
    float4 z = make_float4(0.f, 0.f, 0.f, 0.f);
    for (int i = blockIdx.x * blockDim.x + threadIdx.x; i < NV * COUT / 4; i += stride) {
        ((float4*)g_hgsum)[i] = z;
        ((float4*)g_gsum)[i]  = z;
        if (i < NE * COUT / 4) ((float4*)g_esum)[i] = z;
        if (i < NE)            g_ecnt[i] = 0.f;
        if (i < NV) { g_vcnt_hg[i] = 0.f; g_vcnt_g[i] = 0.f; }
    }
}

// ---------------- fused MLP: h = lrelu(x@W1+b1)@W2 + b2 --------------------
// 128 threads (4 warps), 32-row tile, 8 rows per warp (RPW=8) to amortize
// the W smem wavefronts over 2x more rows -> crossbar demand == FMA2 demand.
#define TILE_R 32
#define RPW    8
#define MLP_THREADS 128
#define S1 (CIN + 2)    // 258: W1T row stride (floats)
#define S2 (CMID + 2)   // 130: W2T row stride
#define SMEM_FLOATS (CMID*S1 + COUT*S2 + TILE_R*CIN + TILE_R*CMID + CMID + COUT)

__global__ __launch_bounds__(MLP_THREADS, 1)
void mlp_kernel(const float* __restrict__ x,
                const float* __restrict__ W1, const float* __restrict__ b1,
                const float* __restrict__ W2, const float* __restrict__ b2) {
    extern __shared__ float sm[];
    float* W1T  = sm;                        // [128][258]  (W1T[j][k] = W1[k][j])
    float* W2T  = W1T + CMID * S1;           // [64][130]
    float* xs   = W2T + COUT * S2;           // [32][256]
    float* mids = xs  + TILE_R * CIN;        // [32][128]
    float* b1s  = mids + TILE_R * CMID;      // [128]
    float* b2s  = b1s + CMID;                // [64]

    int tid = threadIdx.x;
    for (int i = tid; i < CIN * CMID; i += MLP_THREADS) {
        int k = i >> 7, j = i & 127;         // W1[k][j]
        W1T[j * S1 + k] = W1[i];
    }
    for (int i = tid; i < CMID * COUT; i += MLP_THREADS) {
        int k = i >> 6, j = i & 63;          // W2[k][j]
        W2T[j * S2 + k] = W2[i];
    }
    if (tid < CMID) b1s[tid] = b1[tid];
    if (tid < COUT) b2s[tid] = b2[tid];

    int warp = tid >> 5, lane = tid & 31;
    int ntiles = NV / TILE_R;   // 3125, exact

    for (int tile = blockIdx.x; tile < ntiles; tile += gridDim.x) {
        __syncthreads();
        int row0 = tile * TILE_R;
        for (int i = tid; i < TILE_R * CIN / 4; i += MLP_THREADS)
            ((float4*)xs)[i] = ((const float4*)(x + (size_t)row0 * CIN))[i];
        __syncthreads();

        // ---- GEMM1: rows warp*8..+7, cols j = jj*32+lane (jj=0..3) --------
        u64 acc[RPW][4];
#pragma unroll
        for (int r = 0; r < RPW; r++)
#pragma unroll
            for (int jj = 0; jj < 4; jj++) acc[r][jj] = 0ull;

        const float* xrow = xs + (warp * RPW) * CIN;
        const float* wbase = W1T + lane * S1;
#pragma unroll 2
        for (int k = 0; k < CIN; k += 2) {
            u64 wv[4], xv[RPW];
#pragma unroll
            for (int jj = 0; jj < 4; jj++)
                wv[jj] = *(const u64*)(wbase + (jj * 32) * S1 + k);
#pragma unroll
            for (int r = 0; r < RPW; r++)
                xv[r] = *(const u64*)(xrow + r * CIN + k);
#pragma unroll
            for (int r = 0; r < RPW; r++)
#pragma unroll
                for (int jj = 0; jj < 4; jj++)
                    acc[r][jj] = fma2(xv[r], wv[jj], acc[r][jj]);
        }
        // bias + leaky relu -> mids
#pragma unroll
        for (int jj = 0; jj < 4; jj++) {
            int j = jj * 32 + lane;
            float b = b1s[j];
#pragma unroll
            for (int r = 0; r < RPW; r++)
                mids[(warp * RPW + r) * CMID + j] = lrelu(sum2(acc[r][jj]) + b);
        }
        __syncwarp();

        // ---- GEMM2: cols j = jj*32+lane (jj=0..1) -------------------------
        u64 acc2[RPW][2];
#pragma unroll
        for (int r = 0; r < RPW; r++) { acc2[r][0] = 0ull; acc2[r][1] = 0ull; }

        const float* mrow = mids + (warp * RPW) * CMID;
        const float* w2base = W2T + lane * S2;
#pragma unroll 2
        for (int k = 0; k < CMID; k += 2) {
            u64 wv[2], mv[RPW];
#pragma unroll
            for (int jj = 0; jj < 2; jj++)
                wv[jj] = *(const u64*)(w2base + (jj * 32) * S2 + k);
#pragma unroll
            for (int r = 0; r < RPW; r++)
                mv[r] = *(const u64*)(mrow + r * CMID + k);
#pragma unroll
            for (int r = 0; r < RPW; r++)
#pragma unroll
                for (int jj = 0; jj < 2; jj++)
                    acc2[r][jj] = fma2(mv[r], wv[jj], acc2[r][jj]);
        }
#pragma unroll
        for (int jj = 0; jj < 2; jj++) {
            int j = jj * 32 + lane;
            float b = b2s[j];
#pragma unroll
            for (int r = 0; r < RPW; r++)
                g_h[(size_t)(row0 + warp * RPW + r) * COUT + j] = sum2(acc2[r][jj]) + b;
        }
    }
}

// ---------------- scatter-add (mean numerator + count) ---------------------
// 16 threads per pair, float4 per thread, vector reduction atomics.
__global__ void scatter_kernel(const float* __restrict__ feat,
                               const int* __restrict__ sidx,
                               const int* __restrict__ didx,
                               float* __restrict__ sum,
                               float* __restrict__ cnt,
                               int npairs) {
    int t = blockIdx.x * blockDim.x + threadIdx.x;
    int i = t >> 4;
    if (i >= npairs) return;
    int l = t & 15;
    int s = __ldg(sidx + i);
    int d = __ldg(didx + i);
    float4 v = *(const float4*)(feat + (size_t)s * COUT + l * 4);
    float* dst = sum + (size_t)d * COUT + l * 4;
    asm volatile("red.global.add.v4.f32 [%0], {%1,%2,%3,%4};"
                 :: "l"(dst), "f"(v.x), "f"(v.y), "f"(v.z), "f"(v.w)
                 : "memory");
    if (l == 0) atomicAdd(cnt + d, 1.0f);
}

// ---------------- e_feat = e_sum / max(cnt,1) -------------------------------
__global__ void efeat_kernel() {
    int i = blockIdx.x * blockDim.x + threadIdx.x;
    if (i >= NE * COUT) return;
    float c = g_ecnt[i >> 6];
    g_efeat[i] = g_esum[i] / fmaxf(c, 1.0f);
}

// ---------------- final fuse + activation ----------------------------------
__global__ void final_kernel(const float* __restrict__ w, float* __restrict__ out) {
    int t = blockIdx.x * blockDim.x + threadIdx.x;
    if (t >= NV * COUT / 4) return;
    int v = t >> 4;
    float e0 = expf(w[0]), e1 = expf(w[1]);
    float sw0 = e0 / (e0 + e1), sw1 = e1 / (e0 + e1);
    float ih = 1.0f / fmaxf(g_vcnt_hg[v], 1.0f);
    float ig = 1.0f / fmaxf(g_vcnt_g[v], 1.0f);
    float4 hg = ((const float4*)g_hgsum)[t];
    float4 gg = ((const float4*)g_gsum)[t];
    float4 h  = ((const float4*)g_h)[t];
    float4 o;
    o.x = lrelu(sw0 * 0.5f * (gg.x * ig + hg.x * ih) + sw1 * h.x);
    o.y = lrelu(sw0 * 0.5f * (gg.y * ig + hg.y * ih) + sw1 * h.y);
    o.z = lrelu(sw0 * 0.5f * (gg.z * ig + hg.z * ih) + sw1 * h.z);
    o.w = lrelu(sw0 * 0.5f * (gg.w * ig + hg.w * ih) + sw1 * h.w);
    ((float4*)out)[t] = o;
}

// ---------------- launch ----------------------------------------------------
extern "C" void kernel_launch(void* const* d_in, const int* in_sizes, int n_in,
                              void* d_out, int out_size) {
    const float* x    = (const float*)d_in[0];
    const float* W1   = (const float*)d_in[1];
    const float* b1   = (const float*)d_in[2];
    const float* W2   = (const float*)d_in[3];
    const float* b2   = (const float*)d_in[4];
    const float* w    = (const float*)d_in[5];
    const int*   hg_v = (const int*)d_in[6];
    const int*   hg_e = (const int*)d_in[7];
    const int*   g_src= (const int*)d_in[8];
    const int*   g_dst= (const int*)d_in[9];
    float* out = (float*)d_out;

    float *p_h, *p_esum, *p_ecnt, *p_efeat, *p_hgsum, *p_gsum, *p_vch, *p_vcg;
    cudaGetSymbolAddress((void**)&p_h,     g_h);
    cudaGetSymbolAddress((void**)&p_esum,  g_esum);
    cudaGetSymbolAddress((void**)&p_ecnt,  g_ecnt);
    cudaGetSymbolAddress((void**)&p_efeat, g_efeat);
    cudaGetSymbolAddress((void**)&p_hgsum, g_hgsum);
    cudaGetSymbolAddress((void**)&p_gsum,  g_gsum);
    cudaGetSymbolAddress((void**)&p_vch,   g_vcnt_hg);
    cudaGetSymbolAddress((void**)&p_vcg,   g_vcnt_g);

    const size_t smem_bytes = (size_t)SMEM_FLOATS * sizeof(float); // ~210KB
    cudaFuncSetAttribute(mlp_kernel, cudaFuncAttributeMaxDynamicSharedMemorySize,
                         (int)smem_bytes);

    zero_kernel<<<2048, 256>>>();
    mlp_kernel<<<148, MLP_THREADS, smem_bytes>>>(x, W1, b1, W2, b2);

    int sc_blocks = (NP * 16 + 255) / 256;
    // v2e: mean of h over incidence pairs grouped by hyperedge
    scatter_kernel<<<sc_blocks, 256>>>(p_h, hg_v, hg_e, p_esum, p_ecnt, NP);
    efeat_kernel<<<(NE * COUT + 255) / 256, 256>>>();
    // e2v: mean of e_feat over incidence pairs grouped by vertex
    scatter_kernel<<<sc_blocks, 256>>>(p_efeat, hg_e, hg_v, p_hgsum, p_vch, NP);
    // graph: mean of h over edges grouped by destination vertex
    scatter_kernel<<<sc_blocks, 256>>>(p_h, g_src, g_dst, p_gsum, p_vcg, NP);

    final_kernel<<<(NV * COUT / 4 + 255) / 256, 256>>>(w, out);
}

// round 7
// speedup vs baseline: 1.1537x; 1.1209x over previous
#include <cuda_runtime.h>
#include <math.h>

#define NV   100000
#define NE   10000
#define NP   1600000
#define CIN  256
#define CMID 128
#define COUT 64
#define NEG  0.2f

// ---------------- scratch (device globals; no allocation allowed) ----------
__device__ float g_mid[NV * CMID];      // GEMM1 output (post-lrelu)
__device__ float g_h[NV * COUT];        // MLP output h
__device__ float g_esum[NE * COUT];     // hyperedge accumulator
__device__ float g_ecnt[NE];            // hyperedge degree
__device__ float g_efeat[NE * COUT];    // hyperedge mean feature
__device__ float g_hgsum[NV * COUT];    // e2v accumulator
__device__ float g_gsum[NV * COUT];     // graph accumulator
__device__ float g_vcnt_hg[NV];         // vertex incidence degree
__device__ float g_vcnt_g[NV];          // vertex graph in-degree

__device__ __forceinline__ float lrelu(float v) { return v > 0.f ? v : NEG * v; }

typedef unsigned long long u64;

__device__ __forceinline__ u64 fma2(u64 a, u64 b, u64 c) {
    u64 d;
    asm("fma.rn.f32x2 %0, %1, %2, %3;" : "=l"(d) : "l"(a), "l"(b), "l"(c));
    return d;
}
__device__ __forceinline__ float sum2(u64 p) {
    float lo, hi;
    asm("mov.b64 {%0,%1}, %2;" : "=f"(lo), "=f"(hi) : "l"(p));
    return lo + hi;
}

// ---------------- zero accumulators ----------------------------------------
__global__ void zero_kernel() {
    int stride = gridDim.x * blockDim.x;
    float4 z = make_float4(0.f, 0.f, 0.f, 0.f);
    for (int i = blockIdx.x * blockDim.x + threadIdx.x; i < NV * COUT / 4; i += stride) {
        ((float4*)g_hgsum)[i] = z;
        ((float4*)g_gsum)[i]  = z;
        if (i < NE * COUT / 4) ((float4*)g_esum)[i] = z;
        if (i < NE)            g_ecnt[i] = 0.f;
        if (i < NV) { g_vcnt_hg[i] = 0.f; g_vcnt_g[i] = 0.f; }
    }
}

// ================= GEMM1: mid = lrelu(x @ W1 + b1) ==========================
// 256 threads (8 warps), 64-row tile, 8 rows/warp. W1T in smem (transposed,
// stride 260 -> conflict-free 16B LDS), x tile in smem.
#define G1_TILE 64
#define G1_RPW  8
#define S1 (CIN + 4)    // 260: multiple of 4 for 16B alignment, bank-delta 4
#define G1_SMEM (CMID * S1 + G1_TILE * CIN + CMID)

__global__ __launch_bounds__(256, 1)
void gemm1_kernel(const float* __restrict__ x,
                  const float* __restrict__ W1, const float* __restrict__ b1) {
    extern __shared__ float sm[];
    float* W1T = sm;                     // [128][260]: W1T[j][k] = W1[k][j]
    float* xs  = W1T + CMID * S1;        // [64][256]
    float* b1s = xs + G1_TILE * CIN;     // [128]

    int tid = threadIdx.x;
    for (int i = tid; i < CIN * CMID; i += 256) {
        int k = i >> 7, j = i & 127;
        W1T[j * S1 + k] = W1[i];
    }
    if (tid < CMID) b1s[tid] = b1[tid];

    int warp = tid >> 5, lane = tid & 31;
    int ntiles = (NV + G1_TILE - 1) / G1_TILE;   // 1563

    for (int tile = blockIdx.x; tile < ntiles; tile += gridDim.x) {
        __syncthreads();
        int row0 = tile * G1_TILE;
        int nrows = min(G1_TILE, NV - row0);
        for (int i = tid; i < nrows * (CIN / 4); i += 256)
            ((float4*)xs)[i] = ((const float4*)(x + (size_t)row0 * CIN))[i];
        __syncthreads();

        u64 acc[G1_RPW][4];
#pragma unroll
        for (int r = 0; r < G1_RPW; r++)
#pragma unroll
            for (int jj = 0; jj < 4; jj++) acc[r][jj] = 0ull;

        const float* xrow  = xs + (warp * G1_RPW) * CIN;
        const float* wbase = W1T + lane * S1;
#pragma unroll 2
        for (int k = 0; k < CIN; k += 4) {
            ulonglong2 wq[4];
#pragma unroll
            for (int jj = 0; jj < 4; jj++)
                wq[jj] = *(const ulonglong2*)(wbase + (jj * 32) * S1 + k);
            ulonglong2 xq[G1_RPW];
#pragma unroll
            for (int r = 0; r < G1_RPW; r++)
                xq[r] = *(const ulonglong2*)(xrow + r * CIN + k);
#pragma unroll
            for (int r = 0; r < G1_RPW; r++)
#pragma unroll
                for (int jj = 0; jj < 4; jj++) {
                    acc[r][jj] = fma2(xq[r].x, wq[jj].x, acc[r][jj]);
                    acc[r][jj] = fma2(xq[r].y, wq[jj].y, acc[r][jj]);
                }
        }
#pragma unroll
        for (int jj = 0; jj < 4; jj++) {
            int j = jj * 32 + lane;
            float b = b1s[j];
#pragma unroll
            for (int r = 0; r < G1_RPW; r++) {
                int row = row0 + warp * G1_RPW + r;
                if (row < NV)
                    g_mid[(size_t)row * CMID + j] = lrelu(sum2(acc[r][jj]) + b);
            }
        }
    }
}

// ================= GEMM2: h = mid @ W2 + b2 =================================
#define G2_TILE 64
#define G2_RPW  8
#define S2 (CMID + 4)   // 132
#define G2_SMEM (COUT * S2 + G2_TILE * CMID + COUT)

__global__ __launch_bounds__(256, 2)
void gemm2_kernel(const float* __restrict__ W2, const float* __restrict__ b2) {
    extern __shared__ float sm[];
    float* W2T = sm;                     // [64][132]
    float* ms  = W2T + COUT * S2;        // [64][128]
    float* b2s = ms + G2_TILE * CMID;    // [64]

    int tid = threadIdx.x;
    for (int i = tid; i < CMID * COUT; i += 256) {
        int k = i >> 6, j = i & 63;
        W2T[j * S2 + k] = W2[i];
    }
    if (tid < COUT) b2s[tid] = b2[tid];

    int warp = tid >> 5, lane = tid & 31;
    int ntiles = (NV + G2_TILE - 1) / G2_TILE;

    for (int tile = blockIdx.x; tile < ntiles; tile += gridDim.x) {
        __syncthreads();
        int row0 = tile * G2_TILE;
        int nrows = min(G2_TILE, NV - row0);
        for (int i = tid; i < nrows * (CMID / 4); i += 256)
            ((float4*)ms)[i] = ((const float4*)(g_mid + (size_t)row0 * CMID))[i];
        __syncthreads();

        u64 acc[G2_RPW][2];
#pragma unroll
        for (int r = 0; r < G2_RPW; r++) { acc[r][0] = 0ull; acc[r][1] = 0ull; }

        const float* mrow  = ms + (warp * G2_RPW) * CMID;
        const float* wbase = W2T + lane * S2;
#pragma unroll 2
        for (int k = 0; k < CMID; k += 4) {
            ulonglong2 wq[2];
#pragma unroll
            for (int jj = 0; jj < 2; jj++)
                wq[jj] = *(const ulonglong2*)(wbase + (jj * 32) * S2 + k);
            ulonglong2 mq[G2_RPW];
#pragma unroll
            for (int r = 0; r < G2_RPW; r++)
                mq[r] = *(const ulonglong2*)(mrow + r * CMID + k);
#pragma unroll
            for (int r = 0; r < G2_RPW; r++)
#pragma unroll
                for (int jj = 0; jj < 2; jj++) {
                    acc[r][jj] = fma2(mq[r].x, wq[jj].x, acc[r][jj]);
                    acc[r][jj] = fma2(mq[r].y, wq[jj].y, acc[r][jj]);
                }
        }
#pragma unroll
        for (int jj = 0; jj < 2; jj++) {
            int j = jj * 32 + lane;
            float b = b2s[j];
#pragma unroll
            for (int r = 0; r < G2_RPW; r++) {
                int row = row0 + warp * G2_RPW + r;
                if (row < NV)
                    g_h[(size_t)row * COUT + j] = sum2(acc[r][jj]) + b;
            }
        }
    }
}

// ---------------- scatter-add (mean numerator + count) ---------------------
__global__ void scatter_kernel(const float* __restrict__ feat,
                               const int* __restrict__ sidx,
                               const int* __restrict__ didx,
                               float* __restrict__ sum,
                               float* __restrict__ cnt,
                               int npairs) {
    int t = blockIdx.x * blockDim.x + threadIdx.x;
    int i = t >> 4;
    if (i >= npairs) return;
    int l = t & 15;
    int s = __ldg(sidx + i);
    int d = __ldg(didx + i);
    float4 v = *(const float4*)(feat + (size_t)s * COUT + l * 4);
    float* dst = sum + (size_t)d * COUT + l * 4;
    asm volatile("red.global.add.v4.f32 [%0], {%1,%2,%3,%4};"
                 :: "l"(dst), "f"(v.x), "f"(v.y), "f"(v.z), "f"(v.w)
                 : "memory");
    if (l == 0) atomicAdd(cnt + d, 1.0f);
}

// ---------------- e_feat = e_sum / max(cnt,1) -------------------------------
__global__ void efeat_kernel() {
    int i = blockIdx.x * blockDim.x + threadIdx.x;
    if (i >= NE * COUT) return;
    float c = g_ecnt[i >> 6];
    g_efeat[i] = g_esum[i] / fmaxf(c, 1.0f);
}

// ---------------- final fuse + activation ----------------------------------
__global__ void final_kernel(const float* __restrict__ w, float* __restrict__ out) {
    int t = blockIdx.x * blockDim.x + threadIdx.x;
    if (t >= NV * COUT / 4) return;
    int v = t >> 4;
    float e0 = expf(w[0]), e1 = expf(w[1]);
    float sw0 = e0 / (e0 + e1), sw1 = e1 / (e0 + e1);
    float ih = 1.0f / fmaxf(g_vcnt_hg[v], 1.0f);
    float ig = 1.0f / fmaxf(g_vcnt_g[v], 1.0f);
    float4 hg = ((const float4*)g_hgsum)[t];
    float4 gg = ((const float4*)g_gsum)[t];
    float4 h  = ((const float4*)g_h)[t];
    float4 o;
    o.x = lrelu(sw0 * 0.5f * (gg.x * ig + hg.x * ih) + sw1 * h.x);
    o.y = lrelu(sw0 * 0.5f * (gg.y * ig + hg.y * ih) + sw1 * h.y);
    o.z = lrelu(sw0 * 0.5f * (gg.z * ig + hg.z * ih) + sw1 * h.z);
    o.w = lrelu(sw0 * 0.5f * (gg.w * ig + hg.w * ih) + sw1 * h.w);
    ((float4*)out)[t] = o;
}

// ---------------- launch ----------------------------------------------------
extern "C" void kernel_launch(void* const* d_in, const int* in_sizes, int n_in,
                              void* d_out, int out_size) {
    const float* x    = (const float*)d_in[0];
    const float* W1   = (const float*)d_in[1];
    const float* b1   = (const float*)d_in[2];
    const float* W2   = (const float*)d_in[3];
    const float* b2   = (const float*)d_in[4];
    const float* w    = (const float*)d_in[5];
    const int*   hg_v = (const int*)d_in[6];
    const int*   hg_e = (const int*)d_in[7];
    const int*   g_src= (const int*)d_in[8];
    const int*   g_dst= (const int*)d_in[9];
    float* out = (float*)d_out;

    float *p_h, *p_esum, *p_ecnt, *p_efeat, *p_hgsum, *p_gsum, *p_vch, *p_vcg;
    cudaGetSymbolAddress((void**)&p_h,     g_h);
    cudaGetSymbolAddress((void**)&p_esum,  g_esum);
    cudaGetSymbolAddress((void**)&p_ecnt,  g_ecnt);
    cudaGetSymbolAddress((void**)&p_efeat, g_efeat);
    cudaGetSymbolAddress((void**)&p_hgsum, g_hgsum);
    cudaGetSymbolAddress((void**)&p_gsum,  g_gsum);
    cudaGetSymbolAddress((void**)&p_vch,   g_vcnt_hg);
    cudaGetSymbolAddress((void**)&p_vcg,   g_vcnt_g);

    const size_t g1_smem = (size_t)G1_SMEM * sizeof(float); // ~195KB
    const size_t g2_smem = (size_t)G2_SMEM * sizeof(float); // ~66KB
    cudaFuncSetAttribute(gemm1_kernel, cudaFuncAttributeMaxDynamicSharedMemorySize,
                         (int)g1_smem);
    cudaFuncSetAttribute(gemm2_kernel, cudaFuncAttributeMaxDynamicSharedMemorySize,
                         (int)g2_smem);

    zero_kernel<<<2048, 256>>>();
    gemm1_kernel<<<148, 256, g1_smem>>>(x, W1, b1);
    gemm2_kernel<<<296, 256, g2_smem>>>(W2, b2);

    int sc_blocks = (NP * 16 + 255) / 256;
    // v2e: mean of h over incidence pairs grouped by hyperedge
    scatter_kernel<<<sc_blocks, 256>>>(p_h, hg_v, hg_e, p_esum, p_ecnt, NP);
    efeat_kernel<<<(NE * COUT + 255) / 256, 256>>>();
    // e2v: mean of e_feat over incidence pairs grouped by vertex
    scatter_kernel<<<sc_blocks, 256>>>(p_efeat, hg_e, hg_v, p_hgsum, p_vch, NP);
    // graph: mean of h over edges grouped by destination vertex
    scatter_kernel<<<sc_blocks, 256>>>(p_h, g_src, g_dst, p_gsum, p_vcg, NP);

    final_kernel<<<(NV * COUT / 4 + 255) / 256, 256>>>(w, out);
}

// round 9
// speedup vs baseline: 1.4106x; 1.2227x over previous
#include <cuda_runtime.h>
#include <math.h>
#include <cstdint>

#define NV   100000
#define NE   10000
#define NP   1600000
#define CIN  256
#define CMID 128
#define COUT 64
#define NEG  0.2f

// ---------------- scratch (device globals; no allocation allowed) ----------
__device__ float g_mid[NV * CMID];      // GEMM1 output (post-lrelu)
__device__ float g_h[NV * COUT];        // MLP output h
__device__ float g_esum[NE * COUT];     // hyperedge accumulator
__device__ float g_ecnt[NE];            // hyperedge degree
__device__ float g_efeat[NE * COUT];    // hyperedge mean feature
__device__ float g_hgsum[NV * COUT];    // e2v accumulator
__device__ float g_gsum[NV * COUT];     // graph accumulator
__device__ float g_vcnt_hg[NV];         // vertex incidence degree
__device__ float g_vcnt_g[NV];          // vertex graph in-degree

__device__ __forceinline__ float lrelu(float v) { return v > 0.f ? v : NEG * v; }

typedef unsigned long long u64;

__device__ __forceinline__ u64 fma2(u64 a, u64 b, u64 c) {
    u64 d;
    asm("fma.rn.f32x2 %0, %1, %2, %3;" : "=l"(d) : "l"(a), "l"(b), "l"(c));
    return d;
}
__device__ __forceinline__ float sum2(u64 p) {
    float lo, hi;
    asm("mov.b64 {%0,%1}, %2;" : "=f"(lo), "=f"(hi) : "l"(p));
    return lo + hi;
}
__device__ __forceinline__ uint32_t cvt_tf32(float f) {
    uint32_t u;
    asm("cvt.rna.tf32.f32 %0, %1;" : "=r"(u) : "f"(f));
    return u;
}

// ---------------- zero accumulators ----------------------------------------
__global__ void zero_kernel() {
    int stride = gridDim.x * blockDim.x;
    float4 z = make_float4(0.f, 0.f, 0.f, 0.f);
    for (int i = blockIdx.x * blockDim.x + threadIdx.x; i < NV * COUT / 4; i += stride) {
        ((float4*)g_hgsum)[i] = z;
        ((float4*)g_gsum)[i]  = z;
        if (i < NE * COUT / 4) ((float4*)g_esum)[i] = z;
        if (i < NE)            g_ecnt[i] = 0.f;
        if (i < NV) { g_vcnt_hg[i] = 0.f; g_vcnt_g[i] = 0.f; }
    }
}

// ================= GEMM1 (mma.sync tf32): mid = lrelu(x @ W1 + b1) =========
// Persistent 148 CTAs, 256 threads (8 warps: 4 m-blocks x 2 n-blocks).
// B = W1 [256][128] tf32 in smem (pad 132, conflict-free), resident all K.
// A = x tile [128][128] tf32 per K-chunk (2 chunks).
// Warp computes 32 rows x 64 cols = 2 m16 tiles x 8 n8 tiles.
#define G1M   128
#define PADW  132
#define G1_SMEM_BYTES (CIN * PADW * 4 + G1M * PADW * 4 + CMID * 4)  // ~203KB

__global__ __launch_bounds__(256, 1)
void gemm1_tensor(const float* __restrict__ x, const float* __restrict__ W1,
                  const float* __restrict__ b1) {
    extern __shared__ uint32_t sm1[];
    uint32_t* Bs  = sm1;                      // [256][132] tf32
    uint32_t* As  = Bs + CIN * PADW;          // [128][132] tf32
    float*    b1s = (float*)(As + G1M * PADW);// [128]

    int tid = threadIdx.x, wid = tid >> 5, lane = tid & 31;
    int g = lane >> 2, t = lane & 3;
    int m0 = (wid & 3) * 32;      // warp row block
    int n0 = (wid >> 2) * 64;     // warp col block

    // stage B = W1 (row-major [k][n]) in tf32 once
    for (int i = tid; i < CIN * CMID; i += 256) {
        int k = i >> 7, n = i & 127;
        Bs[k * PADW + n] = cvt_tf32(W1[i]);
    }
    if (tid < CMID) b1s[tid] = b1[tid];

    int ntiles = (NV + G1M - 1) / G1M;   // 782
    for (int tile = blockIdx.x; tile < ntiles; tile += gridDim.x) {
        int row0 = tile * G1M;
        float c[2][8][4];
#pragma unroll
        for (int mt = 0; mt < 2; mt++)
#pragma unroll
            for (int nt = 0; nt < 8; nt++)
#pragma unroll
                for (int q = 0; q < 4; q++) c[mt][nt][q] = 0.f;

        for (int kc = 0; kc < 2; kc++) {
            __syncthreads();
            // stage A chunk: 128 rows x 128 k
            for (int i = tid * 4; i < G1M * 128; i += 256 * 4) {
                int r = i >> 7, kk = i & 127;
                int grow = row0 + r;
                float4 xv = (grow < NV)
                    ? *(const float4*)(x + (size_t)grow * CIN + kc * 128 + kk)
                    : make_float4(0.f, 0.f, 0.f, 0.f);
                uint4 tv;
                tv.x = cvt_tf32(xv.x); tv.y = cvt_tf32(xv.y);
                tv.z = cvt_tf32(xv.z); tv.w = cvt_tf32(xv.w);
                *(uint4*)(As + r * PADW + kk) = tv;
            }
            __syncthreads();

#pragma unroll
            for (int s = 0; s < 16; s++) {
                int k0 = s * 8;
                int kb = kc * 128 + k0;
                uint32_t a[2][4];
#pragma unroll
                for (int mt = 0; mt < 2; mt++) {
                    int r = m0 + mt * 16 + g;
                    a[mt][0] = As[r * PADW + k0 + t];
                    a[mt][1] = As[(r + 8) * PADW + k0 + t];
                    a[mt][2] = As[r * PADW + k0 + t + 4];
                    a[mt][3] = As[(r + 8) * PADW + k0 + t + 4];
                }
                uint32_t b[8][2];
#pragma unroll
                for (int nt = 0; nt < 8; nt++) {
                    int n = n0 + nt * 8 + g;
                    b[nt][0] = Bs[(kb + t) * PADW + n];
                    b[nt][1] = Bs[(kb + t + 4) * PADW + n];
                }
#pragma unroll
                for (int mt = 0; mt < 2; mt++)
#pragma unroll
                    for (int nt = 0; nt < 8; nt++) {
                        asm volatile(
                            "mma.sync.aligned.m16n8k8.row.col.f32.tf32.tf32.f32 "
                            "{%0,%1,%2,%3}, {%4,%5,%6,%7}, {%8,%9}, {%0,%1,%2,%3};"
                            : "+f"(c[mt][nt][0]), "+f"(c[mt][nt][1]),
                              "+f"(c[mt][nt][2]), "+f"(c[mt][nt][3])
                            : "r"(a[mt][0]), "r"(a[mt][1]), "r"(a[mt][2]), "r"(a[mt][3]),
                              "r"(b[nt][0]), "r"(b[nt][1]));
                    }
            }
        }

        // epilogue: bias + lrelu -> g_mid
#pragma unroll
        for (int mt = 0; mt < 2; mt++) {
            int r0 = row0 + m0 + mt * 16 + g;
#pragma unroll
            for (int nt = 0; nt < 8; nt++) {
                int col = n0 + nt * 8 + 2 * t;
                float bx = b1s[col], by = b1s[col + 1];
                if (r0 < NV) {
                    float2 o;
                    o.x = lrelu(c[mt][nt][0] + bx);
                    o.y = lrelu(c[mt][nt][1] + by);
                    *(float2*)(g_mid + (size_t)r0 * CMID + col) = o;
                }
                if (r0 + 8 < NV) {
                    float2 o;
                    o.x = lrelu(c[mt][nt][2] + bx);
                    o.y = lrelu(c[mt][nt][3] + by);
                    *(float2*)(g_mid + (size_t)(r0 + 8) * CMID + col) = o;
                }
            }
        }
    }
}

// ================= GEMM2: h = mid @ W2 + b2 (fp32x2, exact) =================
#define G2_TILE 64
#define G2_RPW  8
#define S2 (CMID + 4)   // 132
#define G2_SMEM (COUT * S2 + G2_TILE * CMID + COUT)

__global__ __launch_bounds__(256, 2)
void gemm2_kernel(const float* __restrict__ W2, const float* __restrict__ b2) {
    extern __shared__ float sm[];
    float* W2T = sm;                     // [64][132]
    float* ms  = W2T + COUT * S2;        // [64][128]
    float* b2s = ms + G2_TILE * CMID;    // [64]

    int tid = threadIdx.x;
    for (int i = tid; i < CMID * COUT; i += 256) {
        int k = i >> 6, j = i & 63;
        W2T[j * S2 + k] = W2[i];
    }
    if (tid < COUT) b2s[tid] = b2[tid];

    int warp = tid >> 5, lane = tid & 31;
    int ntiles = (NV + G2_TILE - 1) / G2_TILE;

    for (int tile = blockIdx.x; tile < ntiles; tile += gridDim.x) {
        __syncthreads();
        int row0 = tile * G2_TILE;
        int nrows = min(G2_TILE, NV - row0);
        for (int i = tid; i < nrows * (CMID / 4); i += 256)
            ((float4*)ms)[i] = ((const float4*)(g_mid + (size_t)row0 * CMID))[i];
        __syncthreads();

        u64 acc[G2_RPW][2];
#pragma unroll
        for (int r = 0; r < G2_RPW; r++) { acc[r][0] = 0ull; acc[r][1] = 0ull; }

        const float* mrow  = ms + (warp * G2_RPW) * CMID;
        const float* wbase = W2T + lane * S2;
#pragma unroll 2
        for (int k = 0; k < CMID; k += 4) {
            ulonglong2 wq[2];
#pragma unroll
            for (int jj = 0; jj < 2; jj++)
                wq[jj] = *(const ulonglong2*)(wbase + (jj * 32) * S2 + k);
            ulonglong2 mq[G2_RPW];
#pragma unroll
            for (int r = 0; r < G2_RPW; r++)
                mq[r] = *(const ulonglong2*)(mrow + r * CMID + k);
#pragma unroll
            for (int r = 0; r < G2_RPW; r++)
#pragma unroll
                for (int jj = 0; jj < 2; jj++) {
                    acc[r][jj] = fma2(mq[r].x, wq[jj].x, acc[r][jj]);
                    acc[r][jj] = fma2(mq[r].y, wq[jj].y, acc[r][jj]);
                }
        }
#pragma unroll
        for (int jj = 0; jj < 2; jj++) {
            int j = jj * 32 + lane;
            float b = b2s[j];
#pragma unroll
            for (int r = 0; r < G2_RPW; r++) {
                int row = row0 + warp * G2_RPW + r;
                if (row < NV)
                    g_h[(size_t)row * COUT + j] = sum2(acc[r][jj]) + b;
            }
        }
    }
}

// ---------------- scatter-add (mean numerator + count) ---------------------
__global__ void scatter_kernel(const float* __restrict__ feat,
                               const int* __restrict__ sidx,
                               const int* __restrict__ didx,
                               float* __restrict__ sum,
                               float* __restrict__ cnt,
                               int npairs) {
    int t = blockIdx.x * blockDim.x + threadIdx.x;
    int i = t >> 4;
    if (i >= npairs) return;
    int l = t & 15;
    int s = __ldg(sidx + i);
    int d = __ldg(didx + i);
    float4 v = *(const float4*)(feat + (size_t)s * COUT + l * 4);
    float* dst = sum + (size_t)d * COUT + l * 4;
    asm volatile("red.global.add.v4.f32 [%0], {%1,%2,%3,%4};"
                 :: "l"(dst), "f"(v.x), "f"(v.y), "f"(v.z), "f"(v.w)
                 : "memory");
    if (l == 0) atomicAdd(cnt + d, 1.0f);
}

// ---------------- e_feat = e_sum / max(cnt,1) -------------------------------
__global__ void efeat_kernel() {
    int i = blockIdx.x * blockDim.x + threadIdx.x;
    if (i >= NE * COUT) return;
    float c = g_ecnt[i >> 6];
    g_efeat[i] = g_esum[i] / fmaxf(c, 1.0f);
}

// ---------------- final fuse + activation ----------------------------------
__global__ void final_kernel(const float* __restrict__ w, float* __restrict__ out) {
    int t = blockIdx.x * blockDim.x + threadIdx.x;
    if (t >= NV * COUT / 4) return;
    int v = t >> 4;
    float e0 = expf(w[0]), e1 = expf(w[1]);
    float sw0 = e0 / (e0 + e1), sw1 = e1 / (e0 + e1);
    float ih = 1.0f / fmaxf(g_vcnt_hg[v], 1.0f);
    float ig = 1.0f / fmaxf(g_vcnt_g[v], 1.0f);
    float4 hg = ((const float4*)g_hgsum)[t];
    float4 gg = ((const float4*)g_gsum)[t];
    float4 h  = ((const float4*)g_h)[t];
    float4 o;
    o.x = lrelu(sw0 * 0.5f * (gg.x * ig + hg.x * ih) + sw1 * h.x);
    o.y = lrelu(sw0 * 0.5f * (gg.y * ig + hg.y * ih) + sw1 * h.y);
    o.z = lrelu(sw0 * 0.5f * (gg.z * ig + hg.z * ih) + sw1 * h.z);
    o.w = lrelu(sw0 * 0.5f * (gg.w * ig + hg.w * ih) + sw1 * h.w);
    ((float4*)out)[t] = o;
}

// ---------------- launch ----------------------------------------------------
extern "C" void kernel_launch(void* const* d_in, const int* in_sizes, int n_in,
                              void* d_out, int out_size) {
    const float* x    = (const float*)d_in[0];
    const float* W1   = (const float*)d_in[1];
    const float* b1   = (const float*)d_in[2];
    const float* W2   = (const float*)d_in[3];
    const float* b2   = (const float*)d_in[4];
    const float* w    = (const float*)d_in[5];
    const int*   hg_v = (const int*)d_in[6];
    const int*   hg_e = (const int*)d_in[7];
    const int*   g_src= (const int*)d_in[8];
    const int*   g_dst= (const int*)d_in[9];
    float* out = (float*)d_out;

    float *p_h, *p_esum, *p_ecnt, *p_efeat, *p_hgsum, *p_gsum, *p_vch, *p_vcg;
    cudaGetSymbolAddress((void**)&p_h,     g_h);
    cudaGetSymbolAddress((void**)&p_esum,  g_esum);
    cudaGetSymbolAddress((void**)&p_ecnt,  g_ecnt);
    cudaGetSymbolAddress((void**)&p_efeat, g_efeat);
    cudaGetSymbolAddress((void**)&p_hgsum, g_hgsum);
    cudaGetSymbolAddress((void**)&p_gsum,  g_gsum);
    cudaGetSymbolAddress((void**)&p_vch,   g_vcnt_hg);
    cudaGetSymbolAddress((void**)&p_vcg,   g_vcnt_g);

    cudaFuncSetAttribute(gemm1_tensor, cudaFuncAttributeMaxDynamicSharedMemorySize,
                         G1_SMEM_BYTES);
    const size_t g2_smem = (size_t)G2_SMEM * sizeof(float); // ~66KB
    cudaFuncSetAttribute(gemm2_kernel, cudaFuncAttributeMaxDynamicSharedMemorySize,
                         (int)g2_smem);

    zero_kernel<<<2048, 256>>>();
    gemm1_tensor<<<148, 256, G1_SMEM_BYTES>>>(x, W1, b1);
    gemm2_kernel<<<296, 256, g2_smem>>>(W2, b2);

    int sc_blocks = (NP * 16 + 255) / 256;
    // v2e: mean of h over incidence pairs grouped by hyperedge
    scatter_kernel<<<sc_blocks, 256>>>(p_h, hg_v, hg_e, p_esum, p_ecnt, NP);
    efeat_kernel<<<(NE * COUT + 255) / 256, 256>>>();
    // e2v: mean of e_feat over incidence pairs grouped by vertex
    scatter_kernel<<<sc_blocks, 256>>>(p_efeat, hg_e, hg_v, p_hgsum, p_vch, NP);
    // graph: mean of h over edges grouped by destination vertex
    scatter_kernel<<<sc_blocks, 256>>>(p_h, g_src, g_dst, p_gsum, p_vcg, NP);

    final_kernel<<<(NV * COUT / 4 + 255) / 256, 256>>>(w, out);
}

// round 10
// speedup vs baseline: 1.4688x; 1.0412x over previous
#include <cuda_runtime.h>
#include <math.h>
#include <cstdint>

#define NV   100000
#define NE   10000
#define NP   1600000
#define CIN  256
#define CMID 128
#define COUT 64
#define NEG  0.2f

// ---------------- scratch (device globals; no allocation allowed) ----------
__device__ float g_mid[NV * CMID];      // GEMM1 output (post-lrelu)
__device__ float g_h[NV * COUT];        // MLP output h
__device__ float g_esum[NE * COUT];     // hyperedge accumulator
__device__ float g_ecnt[NE];            // hyperedge degree
__device__ float g_efeat[NE * COUT];    // hyperedge mean feature
__device__ float g_hgsum[NV * COUT];    // e2v accumulator
__device__ float g_gsum[NV * COUT];     // graph accumulator
__device__ float g_vcnt_hg[NV];         // vertex incidence degree
__device__ float g_vcnt_g[NV];          // vertex graph in-degree

__device__ __forceinline__ float lrelu(float v) { return v > 0.f ? v : NEG * v; }

__device__ __forceinline__ uint32_t cvt_tf32(float f) {
    uint32_t u;
    asm("cvt.rna.tf32.f32 %0, %1;" : "=r"(u) : "f"(f));
    return u;
}

// ---------------- zero accumulators ----------------------------------------
__global__ void zero_kernel() {
    int stride = gridDim.x * blockDim.x;
    float4 z = make_float4(0.f, 0.f, 0.f, 0.f);
    for (int i = blockIdx.x * blockDim.x + threadIdx.x; i < NV * COUT / 4; i += stride) {
        ((float4*)g_hgsum)[i] = z;
        ((float4*)g_gsum)[i]  = z;
        if (i < NE * COUT / 4) ((float4*)g_esum)[i] = z;
        if (i < NE)            g_ecnt[i] = 0.f;
        if (i < NV) { g_vcnt_hg[i] = 0.f; g_vcnt_g[i] = 0.f; }
    }
}

// ================= GEMM1 (mma.sync tf32): mid = lrelu(x @ W1 + b1) =========
#define G1M   128
#define PADW  132
#define G1_SMEM_BYTES (CIN * PADW * 4 + G1M * PADW * 4 + CMID * 4)  // ~203KB

__global__ __launch_bounds__(256, 1)
void gemm1_tensor(const float* __restrict__ x, const float* __restrict__ W1,
                  const float* __restrict__ b1) {
    extern __shared__ uint32_t sm1[];
    uint32_t* Bs  = sm1;                      // [256][132] tf32
    uint32_t* As  = Bs + CIN * PADW;          // [128][132] tf32
    float*    b1s = (float*)(As + G1M * PADW);// [128]

    int tid = threadIdx.x, wid = tid >> 5, lane = tid & 31;
    int g = lane >> 2, t = lane & 3;
    int m0 = (wid & 3) * 32;
    int n0 = (wid >> 2) * 64;

    for (int i = tid; i < CIN * CMID; i += 256) {
        int k = i >> 7, n = i & 127;
        Bs[k * PADW + n] = cvt_tf32(W1[i]);
    }
    if (tid < CMID) b1s[tid] = b1[tid];

    int ntiles = (NV + G1M - 1) / G1M;   // 782
    for (int tile = blockIdx.x; tile < ntiles; tile += gridDim.x) {
        int row0 = tile * G1M;
        float c[2][8][4];
#pragma unroll
        for (int mt = 0; mt < 2; mt++)
#pragma unroll
            for (int nt = 0; nt < 8; nt++)
#pragma unroll
                for (int q = 0; q < 4; q++) c[mt][nt][q] = 0.f;

        for (int kc = 0; kc < 2; kc++) {
            __syncthreads();
            for (int i = tid * 4; i < G1M * 128; i += 256 * 4) {
                int r = i >> 7, kk = i & 127;
                int grow = row0 + r;
                float4 xv = (grow < NV)
                    ? *(const float4*)(x + (size_t)grow * CIN + kc * 128 + kk)
                    : make_float4(0.f, 0.f, 0.f, 0.f);
                uint4 tv;
                tv.x = cvt_tf32(xv.x); tv.y = cvt_tf32(xv.y);
                tv.z = cvt_tf32(xv.z); tv.w = cvt_tf32(xv.w);
                *(uint4*)(As + r * PADW + kk) = tv;
            }
            __syncthreads();

#pragma unroll
            for (int s = 0; s < 16; s++) {
                int k0 = s * 8;
                int kb = kc * 128 + k0;
                uint32_t a[2][4];
#pragma unroll
                for (int mt = 0; mt < 2; mt++) {
                    int r = m0 + mt * 16 + g;
                    a[mt][0] = As[r * PADW + k0 + t];
                    a[mt][1] = As[(r + 8) * PADW + k0 + t];
                    a[mt][2] = As[r * PADW + k0 + t + 4];
                    a[mt][3] = As[(r + 8) * PADW + k0 + t + 4];
                }
                uint32_t b[8][2];
#pragma unroll
                for (int nt = 0; nt < 8; nt++) {
                    int n = n0 + nt * 8 + g;
                    b[nt][0] = Bs[(kb + t) * PADW + n];
                    b[nt][1] = Bs[(kb + t + 4) * PADW + n];
                }
#pragma unroll
                for (int mt = 0; mt < 2; mt++)
#pragma unroll
                    for (int nt = 0; nt < 8; nt++) {
                        asm volatile(
                            "mma.sync.aligned.m16n8k8.row.col.f32.tf32.tf32.f32 "
                            "{%0,%1,%2,%3}, {%4,%5,%6,%7}, {%8,%9}, {%0,%1,%2,%3};"
                            : "+f"(c[mt][nt][0]), "+f"(c[mt][nt][1]),
                              "+f"(c[mt][nt][2]), "+f"(c[mt][nt][3])
                            : "r"(a[mt][0]), "r"(a[mt][1]), "r"(a[mt][2]), "r"(a[mt][3]),
                              "r"(b[nt][0]), "r"(b[nt][1]));
                    }
            }
        }

#pragma unroll
        for (int mt = 0; mt < 2; mt++) {
            int r0 = row0 + m0 + mt * 16 + g;
#pragma unroll
            for (int nt = 0; nt < 8; nt++) {
                int col = n0 + nt * 8 + 2 * t;
                float bx = b1s[col], by = b1s[col + 1];
                if (r0 < NV) {
                    float2 o;
                    o.x = lrelu(c[mt][nt][0] + bx);
                    o.y = lrelu(c[mt][nt][1] + by);
                    *(float2*)(g_mid + (size_t)r0 * CMID + col) = o;
                }
                if (r0 + 8 < NV) {
                    float2 o;
                    o.x = lrelu(c[mt][nt][2] + bx);
                    o.y = lrelu(c[mt][nt][3] + by);
                    *(float2*)(g_mid + (size_t)(r0 + 8) * CMID + col) = o;
                }
            }
        }
    }
}

// ================= GEMM2 (mma.sync tf32): h = mid @ W2 + b2 =================
// 8 warps: 4 m-blocks x 2 n-blocks (N=64). Warp: 2 m16 x 4 n8 tiles.
#define G2M    128
#define B2PAD  68
#define G2_SMEM_BYTES (CMID * B2PAD * 4 + G2M * PADW * 4 + COUT * 4)  // ~103KB

__global__ __launch_bounds__(256, 2)
void gemm2_tensor(const float* __restrict__ W2, const float* __restrict__ b2) {
    extern __shared__ uint32_t sm2[];
    uint32_t* Bs  = sm2;                       // [128][68] tf32
    uint32_t* As  = Bs + CMID * B2PAD;         // [128][132] tf32
    float*    b2s = (float*)(As + G2M * PADW); // [64]

    int tid = threadIdx.x, wid = tid >> 5, lane = tid & 31;
    int g = lane >> 2, t = lane & 3;
    int m0 = (wid & 3) * 32;
    int n0 = (wid >> 2) * 32;

    for (int i = tid; i < CMID * COUT; i += 256) {
        int k = i >> 6, n = i & 63;
        Bs[k * B2PAD + n] = cvt_tf32(W2[i]);
    }
    if (tid < COUT) b2s[tid] = b2[tid];

    int ntiles = (NV + G2M - 1) / G2M;
    for (int tile = blockIdx.x; tile < ntiles; tile += gridDim.x) {
        int row0 = tile * G2M;
        __syncthreads();
        for (int i = tid * 4; i < G2M * CMID; i += 256 * 4) {
            int r = i >> 7, kk = i & 127;
            int grow = row0 + r;
            float4 mv = (grow < NV)
                ? *(const float4*)(g_mid + (size_t)grow * CMID + kk)
                : make_float4(0.f, 0.f, 0.f, 0.f);
            uint4 tv;
            tv.x = cvt_tf32(mv.x); tv.y = cvt_tf32(mv.y);
            tv.z = cvt_tf32(mv.z); tv.w = cvt_tf32(mv.w);
            *(uint4*)(As + r * PADW + kk) = tv;
        }
        __syncthreads();

        float c[2][4][4];
#pragma unroll
        for (int mt = 0; mt < 2; mt++)
#pragma unroll
            for (int nt = 0; nt < 4; nt++)
#pragma unroll
                for (int q = 0; q < 4; q++) c[mt][nt][q] = 0.f;

#pragma unroll
        for (int s = 0; s < 16; s++) {
            int k0 = s * 8;
            uint32_t a[2][4];
#pragma unroll
            for (int mt = 0; mt < 2; mt++) {
                int r = m0 + mt * 16 + g;
                a[mt][0] = As[r * PADW + k0 + t];
                a[mt][1] = As[(r + 8) * PADW + k0 + t];
                a[mt][2] = As[r * PADW + k0 + t + 4];
                a[mt][3] = As[(r + 8) * PADW + k0 + t + 4];
            }
            uint32_t b[4][2];
#pragma unroll
            for (int nt = 0; nt < 4; nt++) {
                int n = n0 + nt * 8 + g;
                b[nt][0] = Bs[(k0 + t) * B2PAD + n];
                b[nt][1] = Bs[(k0 + t + 4) * B2PAD + n];
            }
#pragma unroll
            for (int mt = 0; mt < 2; mt++)
#pragma unroll
                for (int nt = 0; nt < 4; nt++) {
                    asm volatile(
                        "mma.sync.aligned.m16n8k8.row.col.f32.tf32.tf32.f32 "
                        "{%0,%1,%2,%3}, {%4,%5,%6,%7}, {%8,%9}, {%0,%1,%2,%3};"
                        : "+f"(c[mt][nt][0]), "+f"(c[mt][nt][1]),
                          "+f"(c[mt][nt][2]), "+f"(c[mt][nt][3])
                        : "r"(a[mt][0]), "r"(a[mt][1]), "r"(a[mt][2]), "r"(a[mt][3]),
                          "r"(b[nt][0]), "r"(b[nt][1]));
                }
        }

#pragma unroll
        for (int mt = 0; mt < 2; mt++) {
            int r0 = row0 + m0 + mt * 16 + g;
#pragma unroll
            for (int nt = 0; nt < 4; nt++) {
                int col = n0 + nt * 8 + 2 * t;
                float bx = b2s[col], by = b2s[col + 1];
                if (r0 < NV) {
                    float2 o;
                    o.x = c[mt][nt][0] + bx;
                    o.y = c[mt][nt][1] + by;
                    *(float2*)(g_h + (size_t)r0 * COUT + col) = o;
                }
                if (r0 + 8 < NV) {
                    float2 o;
                    o.x = c[mt][nt][2] + bx;
                    o.y = c[mt][nt][3] + by;
                    *(float2*)(g_h + (size_t)(r0 + 8) * COUT + col) = o;
                }
            }
        }
    }
}

// ---------------- merged scatter: v2e + graph (both read g_h) --------------
__global__ void scatter2_kernel(const int* __restrict__ hg_v,
                                const int* __restrict__ hg_e,
                                const int* __restrict__ g_srcp,
                                const int* __restrict__ g_dstp,
                                float* __restrict__ esum, float* __restrict__ ecnt,
                                float* __restrict__ gsum, float* __restrict__ gcnt) {
    long long tt = (long long)blockIdx.x * blockDim.x + threadIdx.x;
    const int half = NP * 16;
    const int* sidx; const int* didx; float* sum; float* cnt;
    int t;
    if (tt < half) {
        t = (int)tt;  sidx = hg_v;  didx = hg_e;  sum = esum; cnt = ecnt;
    } else {
        t = (int)(tt - half); sidx = g_srcp; didx = g_dstp; sum = gsum; cnt = gcnt;
    }
    int i = t >> 4;
    if (i >= NP) return;
    int l = t & 15;
    int s = __ldg(sidx + i);
    int d = __ldg(didx + i);
    float4 v = *(const float4*)(g_h + (size_t)s * COUT + l * 4);
    float* dst = sum + (size_t)d * COUT + l * 4;
    asm volatile("red.global.add.v4.f32 [%0], {%1,%2,%3,%4};"
                 :: "l"(dst), "f"(v.x), "f"(v.y), "f"(v.z), "f"(v.w)
                 : "memory");
    if (l == 0) atomicAdd(cnt + d, 1.0f);
}

// ---------------- e2v scatter (reads efeat) ---------------------------------
__global__ void scatter_kernel(const float* __restrict__ feat,
                               const int* __restrict__ sidx,
                               const int* __restrict__ didx,
                               float* __restrict__ sum,
                               float* __restrict__ cnt,
                               int npairs) {
    int t = blockIdx.x * blockDim.x + threadIdx.x;
    int i = t >> 4;
    if (i >= npairs) return;
    int l = t & 15;
    int s = __ldg(sidx + i);
    int d = __ldg(didx + i);
    float4 v = *(const float4*)(feat + (size_t)s * COUT + l * 4);
    float* dst = sum + (size_t)d * COUT + l * 4;
    asm volatile("red.global.add.v4.f32 [%0], {%1,%2,%3,%4};"
                 :: "l"(dst), "f"(v.x), "f"(v.y), "f"(v.z), "f"(v.w)
                 : "memory");
    if (l == 0) atomicAdd(cnt + d, 1.0f);
}

// ---------------- e_feat = e_sum / max(cnt,1) -------------------------------
__global__ void efeat_kernel() {
    int i = blockIdx.x * blockDim.x + threadIdx.x;
    if (i >= NE * COUT) return;
    float c = g_ecnt[i >> 6];
    g_efeat[i] = g_esum[i] / fmaxf(c, 1.0f);
}

// ---------------- final fuse + activation ----------------------------------
__global__ void final_kernel(const float* __restrict__ w, float* __restrict__ out) {
    int t = blockIdx.x * blockDim.x + threadIdx.x;
    if (t >= NV * COUT / 4) return;
    int v = t >> 4;
    float e0 = expf(w[0]), e1 = expf(w[1]);
    float sw0 = e0 / (e0 + e1), sw1 = e1 / (e0 + e1);
    float ih = 1.0f / fmaxf(g_vcnt_hg[v], 1.0f);
    float ig = 1.0f / fmaxf(g_vcnt_g[v], 1.0f);
    float4 hg = ((const float4*)g_hgsum)[t];
    float4 gg = ((const float4*)g_gsum)[t];
    float4 h  = ((const float4*)g_h)[t];
    float4 o;
    o.x = lrelu(sw0 * 0.5f * (gg.x * ig + hg.x * ih) + sw1 * h.x);
    o.y = lrelu(sw0 * 0.5f * (gg.y * ig + hg.y * ih) + sw1 * h.y);
    o.z = lrelu(sw0 * 0.5f * (gg.z * ig + hg.z * ih) + sw1 * h.z);
    o.w = lrelu(sw0 * 0.5f * (gg.w * ig + hg.w * ih) + sw1 * h.w);
    ((float4*)out)[t] = o;
}

// ---------------- launch ----------------------------------------------------
extern "C" void kernel_launch(void* const* d_in, const int* in_sizes, int n_in,
                              void* d_out, int out_size) {
    const float* x    = (const float*)d_in[0];
    const float* W1   = (const float*)d_in[1];
    const float* b1   = (const float*)d_in[2];
    const float* W2   = (const float*)d_in[3];
    const float* b2   = (const float*)d_in[4];
    const float* w    = (const float*)d_in[5];
    const int*   hg_v = (const int*)d_in[6];
    const int*   hg_e = (const int*)d_in[7];
    const int*   g_src= (const int*)d_in[8];
    const int*   g_dst= (const int*)d_in[9];
    float* out = (float*)d_out;

    float *p_esum, *p_ecnt, *p_efeat, *p_hgsum, *p_gsum, *p_vch, *p_vcg;
    cudaGetSymbolAddress((void**)&p_esum,  g_esum);
    cudaGetSymbolAddress((void**)&p_ecnt,  g_ecnt);
    cudaGetSymbolAddress((void**)&p_efeat, g_efeat);
    cudaGetSymbolAddress((void**)&p_hgsum, g_hgsum);
    cudaGetSymbolAddress((void**)&p_gsum,  g_gsum);
    cudaGetSymbolAddress((void**)&p_vch,   g_vcnt_hg);
    cudaGetSymbolAddress((void**)&p_vcg,   g_vcnt_g);

    cudaFuncSetAttribute(gemm1_tensor, cudaFuncAttributeMaxDynamicSharedMemorySize,
                         G1_SMEM_BYTES);
    cudaFuncSetAttribute(gemm2_tensor, cudaFuncAttributeMaxDynamicSharedMemorySize,
                         G2_SMEM_BYTES);

    zero_kernel<<<2048, 256>>>();
    gemm1_tensor<<<148, 256, G1_SMEM_BYTES>>>(x, W1, b1);
    gemm2_tensor<<<296, 256, G2_SMEM_BYTES>>>(W2, b2);

    // v2e + graph scatters in one launch (independent outputs, both read h)
    long long tot = 2LL * NP * 16;
    scatter2_kernel<<<(int)((tot + 255) / 256), 256>>>(hg_v, hg_e, g_src, g_dst,
                                                       p_esum, p_ecnt, p_gsum, p_vcg);
    efeat_kernel<<<(NE * COUT + 255) / 256, 256>>>();
    // e2v: mean of e_feat over incidence pairs grouped by vertex
    scatter_kernel<<<(NP * 16 + 255) / 256, 256>>>(p_efeat, hg_e, hg_v,
                                                   p_hgsum, p_vch, NP);
    final_kernel<<<(NV * COUT / 4 + 255) / 256, 256>>>(w, out);
}

// round 11
// speedup vs baseline: 1.4925x; 1.0161x over previous
#include <cuda_runtime.h>
#include <cuda_bf16.h>
#include <math.h>
#include <cstdint>

#define NV   100000
#define NE   10000
#define NP   1600000
#define CIN  256
#define CMID 128
#define COUT 64
#define NEG  0.2f

// ---------------- scratch (device globals; no allocation allowed) ----------
__device__ float g_mid[NV * CMID];      // GEMM1 output (post-lrelu)
__device__ float g_h[NV * COUT];        // MLP output h (f32, exact path)
__device__ __nv_bfloat16 g_hb[NV * COUT];   // bf16 shadow of h (scatter reads)
__device__ __nv_bfloat16 g_efb[NE * COUT];  // bf16 e_feat (scatter reads)
__device__ float g_esum[NE * COUT];     // hyperedge accumulator
__device__ float g_ecnt[NE];            // hyperedge degree
__device__ float g_hgsum[NV * COUT];    // e2v accumulator
__device__ float g_gsum[NV * COUT];     // graph accumulator
__device__ float g_vcnt_hg[NV];         // vertex incidence degree
__device__ float g_vcnt_g[NV];          // vertex graph in-degree

__device__ __forceinline__ float lrelu(float v) { return v > 0.f ? v : NEG * v; }

__device__ __forceinline__ uint32_t cvt_tf32(float f) {
    uint32_t u;
    asm("cvt.rna.tf32.f32 %0, %1;" : "=r"(u) : "f"(f));
    return u;
}

// ---------------- zero accumulators ----------------------------------------
__global__ void zero_kernel() {
    int stride = gridDim.x * blockDim.x;
    float4 z = make_float4(0.f, 0.f, 0.f, 0.f);
    for (int i = blockIdx.x * blockDim.x + threadIdx.x; i < NV * COUT / 4; i += stride) {
        ((float4*)g_hgsum)[i] = z;
        ((float4*)g_gsum)[i]  = z;
        if (i < NE * COUT / 4) ((float4*)g_esum)[i] = z;
        if (i < NE)            g_ecnt[i] = 0.f;
        if (i < NV) { g_vcnt_hg[i] = 0.f; g_vcnt_g[i] = 0.f; }
    }
}

// ================= GEMM1 (mma.sync tf32): mid = lrelu(x @ W1 + b1) =========
#define G1M   128
#define PADW  132
#define G1_SMEM_BYTES (CIN * PADW * 4 + G1M * PADW * 4 + CMID * 4)  // ~203KB

__global__ __launch_bounds__(256, 1)
void gemm1_tensor(const float* __restrict__ x, const float* __restrict__ W1,
                  const float* __restrict__ b1) {
    extern __shared__ uint32_t sm1[];
    uint32_t* Bs  = sm1;                      // [256][132] tf32
    uint32_t* As  = Bs + CIN * PADW;          // [128][132] tf32
    float*    b1s = (float*)(As + G1M * PADW);// [128]

    int tid = threadIdx.x, wid = tid >> 5, lane = tid & 31;
    int g = lane >> 2, t = lane & 3;
    int m0 = (wid & 3) * 32;
    int n0 = (wid >> 2) * 64;

    for (int i = tid; i < CIN * CMID; i += 256) {
        int k = i >> 7, n = i & 127;
        Bs[k * PADW + n] = cvt_tf32(W1[i]);
    }
    if (tid < CMID) b1s[tid] = b1[tid];

    int ntiles = (NV + G1M - 1) / G1M;   // 782
    for (int tile = blockIdx.x; tile < ntiles; tile += gridDim.x) {
        int row0 = tile * G1M;
        float c[2][8][4];
#pragma unroll
        for (int mt = 0; mt < 2; mt++)
#pragma unroll
            for (int nt = 0; nt < 8; nt++)
#pragma unroll
                for (int q = 0; q < 4; q++) c[mt][nt][q] = 0.f;

        for (int kc = 0; kc < 2; kc++) {
            __syncthreads();
            for (int i = tid * 4; i < G1M * 128; i += 256 * 4) {
                int r = i >> 7, kk = i & 127;
                int grow = row0 + r;
                float4 xv = (grow < NV)
                    ? *(const float4*)(x + (size_t)grow * CIN + kc * 128 + kk)
                    : make_float4(0.f, 0.f, 0.f, 0.f);
                uint4 tv;
                tv.x = cvt_tf32(xv.x); tv.y = cvt_tf32(xv.y);
                tv.z = cvt_tf32(xv.z); tv.w = cvt_tf32(xv.w);
                *(uint4*)(As + r * PADW + kk) = tv;
            }
            __syncthreads();

#pragma unroll
            for (int s = 0; s < 16; s++) {
                int k0 = s * 8;
                int kb = kc * 128 + k0;
                uint32_t a[2][4];
#pragma unroll
                for (int mt = 0; mt < 2; mt++) {
                    int r = m0 + mt * 16 + g;
                    a[mt][0] = As[r * PADW + k0 + t];
                    a[mt][1] = As[(r + 8) * PADW + k0 + t];
                    a[mt][2] = As[r * PADW + k0 + t + 4];
                    a[mt][3] = As[(r + 8) * PADW + k0 + t + 4];
                }
                uint32_t b[8][2];
#pragma unroll
                for (int nt = 0; nt < 8; nt++) {
                    int n = n0 + nt * 8 + g;
                    b[nt][0] = Bs[(kb + t) * PADW + n];
                    b[nt][1] = Bs[(kb + t + 4) * PADW + n];
                }
#pragma unroll
                for (int mt = 0; mt < 2; mt++)
#pragma unroll
                    for (int nt = 0; nt < 8; nt++) {
                        asm volatile(
                            "mma.sync.aligned.m16n8k8.row.col.f32.tf32.tf32.f32 "
                            "{%0,%1,%2,%3}, {%4,%5,%6,%7}, {%8,%9}, {%0,%1,%2,%3};"
                            : "+f"(c[mt][nt][0]), "+f"(c[mt][nt][1]),
                              "+f"(c[mt][nt][2]), "+f"(c[mt][nt][3])
                            : "r"(a[mt][0]), "r"(a[mt][1]), "r"(a[mt][2]), "r"(a[mt][3]),
                              "r"(b[nt][0]), "r"(b[nt][1]));
                    }
            }
        }

#pragma unroll
        for (int mt = 0; mt < 2; mt++) {
            int r0 = row0 + m0 + mt * 16 + g;
#pragma unroll
            for (int nt = 0; nt < 8; nt++) {
                int col = n0 + nt * 8 + 2 * t;
                float bx = b1s[col], by = b1s[col + 1];
                if (r0 < NV) {
                    float2 o;
                    o.x = lrelu(c[mt][nt][0] + bx);
                    o.y = lrelu(c[mt][nt][1] + by);
                    *(float2*)(g_mid + (size_t)r0 * CMID + col) = o;
                }
                if (r0 + 8 < NV) {
                    float2 o;
                    o.x = lrelu(c[mt][nt][2] + bx);
                    o.y = lrelu(c[mt][nt][3] + by);
                    *(float2*)(g_mid + (size_t)(r0 + 8) * CMID + col) = o;
                }
            }
        }
    }
}

// ================= GEMM2 (mma.sync tf32): h = mid @ W2 + b2 =================
#define G2M    128
#define B2PAD  68
#define G2_SMEM_BYTES (CMID * B2PAD * 4 + G2M * PADW * 4 + COUT * 4)  // ~103KB

__global__ __launch_bounds__(256, 2)
void gemm2_tensor(const float* __restrict__ W2, const float* __restrict__ b2) {
    extern __shared__ uint32_t sm2[];
    uint32_t* Bs  = sm2;                       // [128][68] tf32
    uint32_t* As  = Bs + CMID * B2PAD;         // [128][132] tf32
    float*    b2s = (float*)(As + G2M * PADW); // [64]

    int tid = threadIdx.x, wid = tid >> 5, lane = tid & 31;
    int g = lane >> 2, t = lane & 3;
    int m0 = (wid & 3) * 32;
    int n0 = (wid >> 2) * 32;

    for (int i = tid; i < CMID * COUT; i += 256) {
        int k = i >> 6, n = i & 63;
        Bs[k * B2PAD + n] = cvt_tf32(W2[i]);
    }
    if (tid < COUT) b2s[tid] = b2[tid];

    int ntiles = (NV + G2M - 1) / G2M;
    for (int tile = blockIdx.x; tile < ntiles; tile += gridDim.x) {
        int row0 = tile * G2M;
        __syncthreads();
        for (int i = tid * 4; i < G2M * CMID; i += 256 * 4) {
            int r = i >> 7, kk = i & 127;
            int grow = row0 + r;
            float4 mv = (grow < NV)
                ? *(const float4*)(g_mid + (size_t)grow * CMID + kk)
                : make_float4(0.f, 0.f, 0.f, 0.f);
            uint4 tv;
            tv.x = cvt_tf32(mv.x); tv.y = cvt_tf32(mv.y);
            tv.z = cvt_tf32(mv.z); tv.w = cvt_tf32(mv.w);
            *(uint4*)(As + r * PADW + kk) = tv;
        }
        __syncthreads();

        float c[2][4][4];
#pragma unroll
        for (int mt = 0; mt < 2; mt++)
#pragma unroll
            for (int nt = 0; nt < 4; nt++)
#pragma unroll
                for (int q = 0; q < 4; q++) c[mt][nt][q] = 0.f;

#pragma unroll
        for (int s = 0; s < 16; s++) {
            int k0 = s * 8;
            uint32_t a[2][4];
#pragma unroll
            for (int mt = 0; mt < 2; mt++) {
                int r = m0 + mt * 16 + g;
                a[mt][0] = As[r * PADW + k0 + t];
                a[mt][1] = As[(r + 8) * PADW + k0 + t];
                a[mt][2] = As[r * PADW + k0 + t + 4];
                a[mt][3] = As[(r + 8) * PADW + k0 + t + 4];
            }
            uint32_t b[4][2];
#pragma unroll
            for (int nt = 0; nt < 4; nt++) {
                int n = n0 + nt * 8 + g;
                b[nt][0] = Bs[(k0 + t) * B2PAD + n];
                b[nt][1] = Bs[(k0 + t + 4) * B2PAD + n];
            }
#pragma unroll
            for (int mt = 0; mt < 2; mt++)
#pragma unroll
                for (int nt = 0; nt < 4; nt++) {
                    asm volatile(
                        "mma.sync.aligned.m16n8k8.row.col.f32.tf32.tf32.f32 "
                        "{%0,%1,%2,%3}, {%4,%5,%6,%7}, {%8,%9}, {%0,%1,%2,%3};"
                        : "+f"(c[mt][nt][0]), "+f"(c[mt][nt][1]),
                          "+f"(c[mt][nt][2]), "+f"(c[mt][nt][3])
                        : "r"(a[mt][0]), "r"(a[mt][1]), "r"(a[mt][2]), "r"(a[mt][3]),
                          "r"(b[nt][0]), "r"(b[nt][1]));
                }
        }

#pragma unroll
        for (int mt = 0; mt < 2; mt++) {
            int r0 = row0 + m0 + mt * 16 + g;
#pragma unroll
            for (int nt = 0; nt < 4; nt++) {
                int col = n0 + nt * 8 + 2 * t;
                float bx = b2s[col], by = b2s[col + 1];
                if (r0 < NV) {
                    float2 o;
                    o.x = c[mt][nt][0] + bx;
                    o.y = c[mt][nt][1] + by;
                    *(float2*)(g_h + (size_t)r0 * COUT + col) = o;
                    *(__nv_bfloat162*)(g_hb + (size_t)r0 * COUT + col) =
                        __floats2bfloat162_rn(o.x, o.y);
                }
                if (r0 + 8 < NV) {
                    float2 o;
                    o.x = c[mt][nt][2] + bx;
                    o.y = c[mt][nt][3] + by;
                    *(float2*)(g_h + (size_t)(r0 + 8) * COUT + col) = o;
                    *(__nv_bfloat162*)(g_hb + (size_t)(r0 + 8) * COUT + col) =
                        __floats2bfloat162_rn(o.x, o.y);
                }
            }
        }
    }
}

// ---------------- bf16-read scatter helper ----------------------------------
__device__ __forceinline__ void scat_bf16(const __nv_bfloat16* __restrict__ feat,
                                          int s, int d, int l,
                                          float* __restrict__ sum,
                                          float* __restrict__ cnt) {
    // lane l owns cols 4l..4l+3; bf16 row = 128B, lane reads 8B
    uint2 raw = *(const uint2*)(feat + (size_t)s * COUT + l * 4);
    float2 lo = __bfloat1622float2(*(__nv_bfloat162*)&raw.x);
    float2 hi = __bfloat1622float2(*(__nv_bfloat162*)&raw.y);
    float* dst = sum + (size_t)d * COUT + l * 4;
    asm volatile("red.global.add.v4.f32 [%0], {%1,%2,%3,%4};"
                 :: "l"(dst), "f"(lo.x), "f"(lo.y), "f"(hi.x), "f"(hi.y)
                 : "memory");
    if (l == 0) atomicAdd(cnt + d, 1.0f);
}

// ---------------- merged scatter: v2e + graph (both read g_hb) --------------
__global__ void scatter2_kernel(const int* __restrict__ hg_v,
                                const int* __restrict__ hg_e,
                                const int* __restrict__ g_srcp,
                                const int* __restrict__ g_dstp,
                                float* __restrict__ esum, float* __restrict__ ecnt,
                                float* __restrict__ gsum, float* __restrict__ gcnt) {
    long long tt = (long long)blockIdx.x * blockDim.x + threadIdx.x;
    const int half = NP * 16;
    const int* sidx; const int* didx; float* sum; float* cnt;
    int t;
    if (tt < half) {
        t = (int)tt;  sidx = hg_v;  didx = hg_e;  sum = esum; cnt = ecnt;
    } else {
        t = (int)(tt - half); sidx = g_srcp; didx = g_dstp; sum = gsum; cnt = gcnt;
    }
    int i = t >> 4;
    if (i >= NP) return;
    int l = t & 15;
    scat_bf16(g_hb, __ldg(sidx + i), __ldg(didx + i), l, sum, cnt);
}

// ---------------- e2v scatter (reads bf16 efeat) ----------------------------
__global__ void scatter_e2v_kernel(const int* __restrict__ hg_e,
                                   const int* __restrict__ hg_v,
                                   float* __restrict__ sum,
                                   float* __restrict__ cnt) {
    int t = blockIdx.x * blockDim.x + threadIdx.x;
    int i = t >> 4;
    if (i >= NP) return;
    int l = t & 15;
    scat_bf16(g_efb, __ldg(hg_e + i), __ldg(hg_v + i), l, sum, cnt);
}

// ---------------- e_feat(bf16) = e_sum / max(cnt,1) -------------------------
__global__ void efeat_kernel() {
    int i = blockIdx.x * blockDim.x + threadIdx.x;   // bf16x2 elements
    if (i >= NE * COUT / 2) return;
    float c = fmaxf(g_ecnt[i >> 5], 1.0f);
    float inv = 1.0f / c;
    float2 v = ((const float2*)g_esum)[i];
    ((__nv_bfloat162*)g_efb)[i] = __floats2bfloat162_rn(v.x * inv, v.y * inv);
}

// ---------------- final fuse + activation ----------------------------------
__global__ void final_kernel(const float* __restrict__ w, float* __restrict__ out) {
    int t = blockIdx.x * blockDim.x + threadIdx.x;
    if (t >= NV * COUT / 4) return;
    int v = t >> 4;
    float e0 = expf(w[0]), e1 = expf(w[1]);
    float sw0 = e0 / (e0 + e1), sw1 = e1 / (e0 + e1);
    float ih = 1.0f / fmaxf(g_vcnt_hg[v], 1.0f);
    float ig = 1.0f / fmaxf(g_vcnt_g[v], 1.0f);
    float4 hg = ((const float4*)g_hgsum)[t];
    float4 gg = ((const float4*)g_gsum)[t];
    float4 h  = ((const float4*)g_h)[t];
    float4 o;
    o.x = lrelu(sw0 * 0.5f * (gg.x * ig + hg.x * ih) + sw1 * h.x);
    o.y = lrelu(sw0 * 0.5f * (gg.y * ig + hg.y * ih) + sw1 * h.y);
    o.z = lrelu(sw0 * 0.5f * (gg.z * ig + hg.z * ih) + sw1 * h.z);
    o.w = lrelu(sw0 * 0.5f * (gg.w * ig + hg.w * ih) + sw1 * h.w);
    ((float4*)out)[t] = o;
}

// ---------------- launch ----------------------------------------------------
extern "C" void kernel_launch(void* const* d_in, const int* in_sizes, int n_in,
                              void* d_out, int out_size) {
    const float* x    = (const float*)d_in[0];
    const float* W1   = (const float*)d_in[1];
    const float* b1   = (const float*)d_in[2];
    const float* W2   = (const float*)d_in[3];
    const float* b2   = (const float*)d_in[4];
    const float* w    = (const float*)d_in[5];
    const int*   hg_v = (const int*)d_in[6];
    const int*   hg_e = (const int*)d_in[7];
    const int*   g_src= (const int*)d_in[8];
    const int*   g_dst= (const int*)d_in[9];
    float* out = (float*)d_out;

    float *p_esum, *p_ecnt, *p_hgsum, *p_gsum, *p_vch, *p_vcg;
    cudaGetSymbolAddress((void**)&p_esum,  g_esum);
    cudaGetSymbolAddress((void**)&p_ecnt,  g_ecnt);
    cudaGetSymbolAddress((void**)&p_hgsum, g_hgsum);
    cudaGetSymbolAddress((void**)&p_gsum,  g_gsum);
    cudaGetSymbolAddress((void**)&p_vch,   g_vcnt_hg);
    cudaGetSymbolAddress((void**)&p_vcg,   g_vcnt_g);

    cudaFuncSetAttribute(gemm1_tensor, cudaFuncAttributeMaxDynamicSharedMemorySize,
                         G1_SMEM_BYTES);
    cudaFuncSetAttribute(gemm2_tensor, cudaFuncAttributeMaxDynamicSharedMemorySize,
                         G2_SMEM_BYTES);

    zero_kernel<<<2048, 256>>>();
    gemm1_tensor<<<148, 256, G1_SMEM_BYTES>>>(x, W1, b1);
    gemm2_tensor<<<296, 256, G2_SMEM_BYTES>>>(W2, b2);

    // v2e + graph scatters in one launch (both read g_hb)
    long long tot = 2LL * NP * 16;
    scatter2_kernel<<<(int)((tot + 255) / 256), 256>>>(hg_v, hg_e, g_src, g_dst,
                                                       p_esum, p_ecnt, p_gsum, p_vcg);
    efeat_kernel<<<(NE * COUT / 2 + 255) / 256, 256>>>();
    scatter_e2v_kernel<<<(NP * 16 + 255) / 256, 256>>>(hg_e, hg_v, p_hgsum, p_vch);
    final_kernel<<<(NV * COUT / 4 + 255) / 256, 256>>>(w, out);
}

// round 12
// speedup vs baseline: 1.5139x; 1.0143x over previous
#include <cuda_runtime.h>
#include <cuda_bf16.h>
#include <math.h>
#include <cstdint>

#define NV   100000
#define NE   10000
#define NP   1600000
#define CIN  256
#define CMID 128
#define COUT 64
#define NEG  0.2f

// ---------------- scratch (device globals; no allocation allowed) ----------
__device__ float g_h[NV * COUT];        // MLP output h (f32, exact path)
__device__ __nv_bfloat16 g_hb[NV * COUT];   // bf16 shadow of h (scatter reads)
__device__ __nv_bfloat16 g_efb[NE * COUT];  // bf16 e_feat (scatter reads)
__device__ float g_esum[NE * COUT];     // hyperedge accumulator
__device__ float g_ecnt[NE];            // hyperedge degree
__device__ float g_hgsum[NV * COUT];    // e2v accumulator
__device__ float g_gsum[NV * COUT];     // graph accumulator
__device__ float g_vcnt_hg[NV];         // vertex incidence degree
__device__ float g_vcnt_g[NV];          // vertex graph in-degree

__device__ __forceinline__ float lrelu(float v) { return v > 0.f ? v : NEG * v; }

__device__ __forceinline__ uint32_t cvt_tf32(float f) {
    uint32_t u;
    asm("cvt.rna.tf32.f32 %0, %1;" : "=r"(u) : "f"(f));
    return u;
}
__device__ __forceinline__ void mma_tf32(float* c, const uint32_t* a,
                                         const uint32_t* b) {
    asm volatile(
        "mma.sync.aligned.m16n8k8.row.col.f32.tf32.tf32.f32 "
        "{%0,%1,%2,%3}, {%4,%5,%6,%7}, {%8,%9}, {%0,%1,%2,%3};"
        : "+f"(c[0]), "+f"(c[1]), "+f"(c[2]), "+f"(c[3])
        : "r"(a[0]), "r"(a[1]), "r"(a[2]), "r"(a[3]), "r"(b[0]), "r"(b[1]));
}

// ---------------- zero accumulators ----------------------------------------
__global__ void zero_kernel() {
    int stride = gridDim.x * blockDim.x;
    float4 z = make_float4(0.f, 0.f, 0.f, 0.f);
    for (int i = blockIdx.x * blockDim.x + threadIdx.x; i < NV * COUT / 4; i += stride) {
        ((float4*)g_hgsum)[i] = z;
        ((float4*)g_gsum)[i]  = z;
        if (i < NE * COUT / 4) ((float4*)g_esum)[i] = z;
        if (i < NE)            g_ecnt[i] = 0.f;
        if (i < NV) { g_vcnt_hg[i] = 0.f; g_vcnt_g[i] = 0.f; }
    }
}

// ========== fused MLP (mma.sync tf32): h = lrelu(x@W1+b1)@W2 + b2 ==========
// Persistent 148 CTAs, 256 threads. W1 [256][132] + W2 [128][68] resident.
// A staged per tile in 4 K-chunks of 64 into As [128][68]. After GEMM1,
// mid relays through As in two 64-col halves (warps 0-3 own cols 0-63,
// warps 4-7 own cols 64-127 == GEMM2's K-split).
#define GM    128
#define PW1   132
#define PA    68
#define SM_W1 0
#define SM_W2 (CIN * PW1)                    // 33792
#define SM_AS (SM_W2 + CMID * PA)            // 42496
#define SM_B1 (SM_AS + GM * PA)              // 51200
#define SM_B2 (SM_B1 + CMID)
#define GF_WORDS (SM_B2 + COUT)              // 51392 words ~ 205.6KB
#define GF_SMEM_BYTES (GF_WORDS * 4)

__global__ __launch_bounds__(256, 1)
void gemm_fused(const float* __restrict__ x, const float* __restrict__ W1,
                const float* __restrict__ b1, const float* __restrict__ W2,
                const float* __restrict__ b2) {
    extern __shared__ uint32_t sm[];
    uint32_t* W1s = sm + SM_W1;              // [256][132] tf32
    uint32_t* W2s = sm + SM_W2;              // [128][68]  tf32
    uint32_t* As  = sm + SM_AS;              // [128][68]  tf32
    float*    b1s = (float*)(sm + SM_B1);    // [128]
    float*    b2s = (float*)(sm + SM_B2);    // [64]

    int tid = threadIdx.x, wid = tid >> 5, lane = tid & 31;
    int g = lane >> 2, t = lane & 3;
    int m0 = (wid & 3) * 32;        // rows (both GEMMs)
    int n1 = (wid >> 2) * 64;       // GEMM1 col block (also its mid half)
    int n2 = (wid >> 2) * 32;       // GEMM2 col block

    for (int i = tid; i < CIN * CMID; i += 256) {
        int k = i >> 7, n = i & 127;
        W1s[k * PW1 + n] = cvt_tf32(W1[i]);
    }
    for (int i = tid; i < CMID * COUT; i += 256) {
        int k = i >> 6, n = i & 63;
        W2s[k * PA + n] = cvt_tf32(W2[i]);
    }
    if (tid < CMID) b1s[tid] = b1[tid];
    if (tid < COUT) b2s[tid] = b2[tid];

    int ntiles = (NV + GM - 1) / GM;   // 782
    for (int tile = blockIdx.x; tile < ntiles; tile += gridDim.x) {
        int row0 = tile * GM;

        // ---------------- GEMM1 ----------------
        float c1[2][8][4];
#pragma unroll
        for (int mt = 0; mt < 2; mt++)
#pragma unroll
            for (int nt = 0; nt < 8; nt++)
#pragma unroll
                for (int q = 0; q < 4; q++) c1[mt][nt][q] = 0.f;

        for (int kc = 0; kc < 4; kc++) {
            __syncthreads();
            // stage A chunk: 128 rows x 64 k
            for (int i = tid * 4; i < GM * 64; i += 256 * 4) {
                int r = i >> 6, kk = i & 63;
                int grow = row0 + r;
                float4 xv = (grow < NV)
                    ? *(const float4*)(x + (size_t)grow * CIN + kc * 64 + kk)
                    : make_float4(0.f, 0.f, 0.f, 0.f);
                uint4 tv;
                tv.x = cvt_tf32(xv.x); tv.y = cvt_tf32(xv.y);
                tv.z = cvt_tf32(xv.z); tv.w = cvt_tf32(xv.w);
                *(uint4*)(As + r * PA + kk) = tv;
            }
            __syncthreads();

#pragma unroll
            for (int s = 0; s < 8; s++) {
                int k0 = s * 8;
                int kb = kc * 64 + k0;
                uint32_t a[2][4];
#pragma unroll
                for (int mt = 0; mt < 2; mt++) {
                    int r = m0 + mt * 16 + g;
                    a[mt][0] = As[r * PA + k0 + t];
                    a[mt][1] = As[(r + 8) * PA + k0 + t];
                    a[mt][2] = As[r * PA + k0 + t + 4];
                    a[mt][3] = As[(r + 8) * PA + k0 + t + 4];
                }
                uint32_t b[8][2];
#pragma unroll
                for (int nt = 0; nt < 8; nt++) {
                    int n = n1 + nt * 8 + g;
                    b[nt][0] = W1s[(kb + t) * PW1 + n];
                    b[nt][1] = W1s[(kb + t + 4) * PW1 + n];
                }
#pragma unroll
                for (int mt = 0; mt < 2; mt++)
#pragma unroll
                    for (int nt = 0; nt < 8; nt++)
                        mma_tf32(c1[mt][nt], a[mt], b[nt]);
            }
        }

        // ---------------- GEMM2 (two K-halves relayed through As) ----------
        float c2[2][4][4];
#pragma unroll
        for (int mt = 0; mt < 2; mt++)
#pragma unroll
            for (int nt = 0; nt < 4; nt++)
#pragma unroll
                for (int q = 0; q < 4; q++) c2[mt][nt][q] = 0.f;

#pragma unroll
        for (int half = 0; half < 2; half++) {
            __syncthreads();
            if ((wid >> 2) == half) {
                // deposit my mid half (bias + lrelu + cvt) into As, local cols 0-63
#pragma unroll
                for (int mt = 0; mt < 2; mt++) {
                    int r = m0 + mt * 16 + g;
#pragma unroll
                    for (int nt = 0; nt < 8; nt++) {
                        int col = nt * 8 + 2 * t;           // 0..63 local
                        float bx = b1s[n1 + col], by = b1s[n1 + col + 1];
                        uint2 v0, v1;
                        v0.x = cvt_tf32(lrelu(c1[mt][nt][0] + bx));
                        v0.y = cvt_tf32(lrelu(c1[mt][nt][1] + by));
                        v1.x = cvt_tf32(lrelu(c1[mt][nt][2] + bx));
                        v1.y = cvt_tf32(lrelu(c1[mt][nt][3] + by));
                        *(uint2*)(As + r * PA + col) = v0;
                        *(uint2*)(As + (r + 8) * PA + col) = v1;
                    }
                }
            }
            __syncthreads();
#pragma unroll
            for (int s = 0; s < 8; s++) {
                int k0 = s * 8;                  // local k in this half
                int kb = half * 64 + k0;         // W2 row
                uint32_t a[2][4];
#pragma unroll
                for (int mt = 0; mt < 2; mt++) {
                    int r = m0 + mt * 16 + g;
                    a[mt][0] = As[r * PA + k0 + t];
                    a[mt][1] = As[(r + 8) * PA + k0 + t];
                    a[mt][2] = As[r * PA + k0 + t + 4];
                    a[mt][3] = As[(r + 8) * PA + k0 + t + 4];
                }
                uint32_t b[4][2];
#pragma unroll
                for (int nt = 0; nt < 4; nt++) {
                    int n = n2 + nt * 8 + g;
                    b[nt][0] = W2s[(kb + t) * PA + n];
                    b[nt][1] = W2s[(kb + t + 4) * PA + n];
                }
#pragma unroll
                for (int mt = 0; mt < 2; mt++)
#pragma unroll
                    for (int nt = 0; nt < 4; nt++)
                        mma_tf32(c2[mt][nt], a[mt], b[nt]);
            }
        }

        // ---------------- epilogue: h -> g_h (f32) + g_hb (bf16) -----------
#pragma unroll
        for (int mt = 0; mt < 2; mt++) {
            int r0 = row0 + m0 + mt * 16 + g;
#pragma unroll
            for (int nt = 0; nt < 4; nt++) {
                int col = n2 + nt * 8 + 2 * t;
                float bx = b2s[col], by = b2s[col + 1];
                if (r0 < NV) {
                    float2 o; o.x = c2[mt][nt][0] + bx; o.y = c2[mt][nt][1] + by;
                    *(float2*)(g_h + (size_t)r0 * COUT + col) = o;
                    *(__nv_bfloat162*)(g_hb + (size_t)r0 * COUT + col) =
                        __floats2bfloat162_rn(o.x, o.y);
                }
                if (r0 + 8 < NV) {
                    float2 o; o.x = c2[mt][nt][2] + bx; o.y = c2[mt][nt][3] + by;
                    *(float2*)(g_h + (size_t)(r0 + 8) * COUT + col) = o;
                    *(__nv_bfloat162*)(g_hb + (size_t)(r0 + 8) * COUT + col) =
                        __floats2bfloat162_rn(o.x, o.y);
                }
            }
        }
    }
}

// ---------------- bf16-read scatter helper ----------------------------------
__device__ __forceinline__ void scat_bf16(const __nv_bfloat16* __restrict__ feat,
                                          int s, int d, int l,
                                          float* __restrict__ sum,
                                          float* __restrict__ cnt) {
    uint2 raw = *(const uint2*)(feat + (size_t)s * COUT + l * 4);
    float2 lo = __bfloat1622float2(*(__nv_bfloat162*)&raw.x);
    float2 hi = __bfloat1622float2(*(__nv_bfloat162*)&raw.y);
    float* dst = sum + (size_t)d * COUT + l * 4;
    asm volatile("red.global.add.v4.f32 [%0], {%1,%2,%3,%4};"
                 :: "l"(dst), "f"(lo.x), "f"(lo.y), "f"(hi.x), "f"(hi.y)
                 : "memory");
    if (l == 0) atomicAdd(cnt + d, 1.0f);
}

// ---------------- merged scatter: v2e + graph (both read g_hb) --------------
__global__ void scatter2_kernel(const int* __restrict__ hg_v,
                                const int* __restrict__ hg_e,
                                const int* __restrict__ g_srcp,
                                const int* __restrict__ g_dstp,
                                float* __restrict__ esum, float* __restrict__ ecnt,
                                float* __restrict__ gsum, float* __restrict__ gcnt) {
    long long tt = (long long)blockIdx.x * blockDim.x + threadIdx.x;
    const int half = NP * 16;
    const int* sidx; const int* didx; float* sum; float* cnt;
    int t;
    if (tt < half) {
        t = (int)tt;  sidx = hg_v;  didx = hg_e;  sum = esum; cnt = ecnt;
    } else {
        t = (int)(tt - half); sidx = g_srcp; didx = g_dstp; sum = gsum; cnt = gcnt;
    }
    int i = t >> 4;
    if (i >= NP) return;
    int l = t & 15;
    scat_bf16(g_hb, __ldg(sidx + i), __ldg(didx + i), l, sum, cnt);
}

// ---------------- e2v scatter (reads bf16 efeat) ----------------------------
__global__ void scatter_e2v_kernel(const int* __restrict__ hg_e,
                                   const int* __restrict__ hg_v,
                                   float* __restrict__ sum,
                                   float* __restrict__ cnt) {
    int t = blockIdx.x * blockDim.x + threadIdx.x;
    int i = t >> 4;
    if (i >= NP) return;
    int l = t & 15;
    scat_bf16(g_efb, __ldg(hg_e + i), __ldg(hg_v + i), l, sum, cnt);
}

// ---------------- e_feat(bf16) = e_sum / max(cnt,1) -------------------------
__global__ void efeat_kernel() {
    int i = blockIdx.x * blockDim.x + threadIdx.x;   // bf16x2 elements
    if (i >= NE * COUT / 2) return;
    float c = fmaxf(g_ecnt[i >> 5], 1.0f);
    float inv = 1.0f / c;
    float2 v = ((const float2*)g_esum)[i];
    ((__nv_bfloat162*)g_efb)[i] = __floats2bfloat162_rn(v.x * inv, v.y * inv);
}

// ---------------- final fuse + activation ----------------------------------
__global__ void final_kernel(const float* __restrict__ w, float* __restrict__ out) {
    int t = blockIdx.x * blockDim.x + threadIdx.x;
    if (t >= NV * COUT / 4) return;
    int v = t >> 4;
    float e0 = expf(w[0]), e1 = expf(w[1]);
    float sw0 = e0 / (e0 + e1), sw1 = e1 / (e0 + e1);
    float ih = 1.0f / fmaxf(g_vcnt_hg[v], 1.0f);
    float ig = 1.0f / fmaxf(g_vcnt_g[v], 1.0f);
    float4 hg = ((const float4*)g_hgsum)[t];
    float4 gg = ((const float4*)g_gsum)[t];
    float4 h  = ((const float4*)g_h)[t];
    float4 o;
    o.x = lrelu(sw0 * 0.5f * (gg.x * ig + hg.x * ih) + sw1 * h.x);
    o.y = lrelu(sw0 * 0.5f * (gg.y * ig + hg.y * ih) + sw1 * h.y);
    o.z = lrelu(sw0 * 0.5f * (gg.z * ig + hg.z * ih) + sw1 * h.z);
    o.w = lrelu(sw0 * 0.5f * (gg.w * ig + hg.w * ih) + sw1 * h.w);
    ((float4*)out)[t] = o;
}

// ---------------- launch ----------------------------------------------------
extern "C" void kernel_launch(void* const* d_in, const int* in_sizes, int n_in,
                              void* d_out, int out_size) {
    const float* x    = (const float*)d_in[0];
    const float* W1   = (const float*)d_in[1];
    const float* b1   = (const float*)d_in[2];
    const float* W2   = (const float*)d_in[3];
    const float* b2   = (const float*)d_in[4];
    const float* w    = (const float*)d_in[5];
    const int*   hg_v = (const int*)d_in[6];
    const int*   hg_e = (const int*)d_in[7];
    const int*   g_src= (const int*)d_in[8];
    const int*   g_dst= (const int*)d_in[9];
    float* out = (float*)d_out;

    float *p_esum, *p_ecnt, *p_hgsum, *p_gsum, *p_vch, *p_vcg;
    cudaGetSymbolAddress((void**)&p_esum,  g_esum);
    cudaGetSymbolAddress((void**)&p_ecnt,  g_ecnt);
    cudaGetSymbolAddress((void**)&p_hgsum, g_hgsum);
    cudaGetSymbolAddress((void**)&p_gsum,  g_gsum);
    cudaGetSymbolAddress((void**)&p_vch,   g_vcnt_hg);
    cudaGetSymbolAddress((void**)&p_vcg,   g_vcnt_g);

    cudaFuncSetAttribute(gemm_fused, cudaFuncAttributeMaxDynamicSharedMemorySize,
                         GF_SMEM_BYTES);

    zero_kernel<<<2048, 256>>>();
    gemm_fused<<<148, 256, GF_SMEM_BYTES>>>(x, W1, b1, W2, b2);

    // v2e + graph scatters in one launch (both read g_hb)
    long long tot = 2LL * NP * 16;
    scatter2_kernel<<<(int)((tot + 255) / 256), 256>>>(hg_v, hg_e, g_src, g_dst,
                                                       p_esum, p_ecnt, p_gsum, p_vcg);
    efeat_kernel<<<(NE * COUT / 2 + 255) / 256, 256>>>();
    scatter_e2v_kernel<<<(NP * 16 + 255) / 256, 256>>>(hg_e, hg_v, p_hgsum, p_vch);
    final_kernel<<<(NV * COUT / 4 + 255) / 256, 256>>>(w, out);
}

// round 13
// speedup vs baseline: 1.5364x; 1.0149x over previous
#include <cuda_runtime.h>
#include <cuda_bf16.h>
#include <math.h>
#include <cstdint>

#define NV   100000
#define NE   10000
#define NP   1600000
#define CIN  256
#define CMID 128
#define COUT 64
#define NEG  0.2f

// ---------------- scratch (device globals; no allocation allowed) ----------
__device__ float g_h[NV * COUT];        // MLP output h (f32, exact path)
__device__ __nv_bfloat16 g_hb[NV * COUT];   // bf16 shadow of h (scatter reads)
__device__ __nv_bfloat16 g_efb[NE * COUT];  // bf16 e_feat (scatter reads)
__device__ float g_esum[NE * COUT];     // hyperedge accumulator
__device__ float g_ecnt[NE];            // hyperedge degree
__device__ float g_hgsum[NV * COUT];    // e2v accumulator
__device__ float g_gsum[NV * COUT];     // graph accumulator
__device__ float g_vcnt_hg[NV];         // vertex incidence degree
__device__ float g_vcnt_g[NV];          // vertex graph in-degree

__device__ __forceinline__ float lrelu(float v) { return v > 0.f ? v : NEG * v; }

__device__ __forceinline__ uint32_t cvt_tf32(float f) {
    uint32_t u;
    asm("cvt.rna.tf32.f32 %0, %1;" : "=r"(u) : "f"(f));
    return u;
}
__device__ __forceinline__ void mma_tf32(float* c, const uint32_t* a,
                                         const uint32_t* b) {
    asm volatile(
        "mma.sync.aligned.m16n8k8.row.col.f32.tf32.tf32.f32 "
        "{%0,%1,%2,%3}, {%4,%5,%6,%7}, {%8,%9}, {%0,%1,%2,%3};"
        : "+f"(c[0]), "+f"(c[1]), "+f"(c[2]), "+f"(c[3])
        : "r"(a[0]), "r"(a[1]), "r"(a[2]), "r"(a[3]), "r"(b[0]), "r"(b[1]));
}

// ========== fused MLP (mma.sync tf32): h = lrelu(x@W1+b1)@W2 + b2 ==========
// Persistent 148 CTAs, 256 threads. Weights resident in FRAGMENT-PAIRED smem
// layout: row (kstep*4+t) holds uint2 {W[8k+t][n], W[8k+t+4][n]} -> each
// lane's b-fragment is one conflict-free LDS.64 (row strides 264/136 words:
// residue 8 mod 32 -> (8t + 2g + e) covers all 32 banks per phase).
// Accumulator zeroing fused at kernel head (drops the zero launch).
#define GM     128
#define PW1R   264          // W1p row stride in words (128 uint2 + 4 pad)
#define PW2R   136          // W2p row stride in words (64 uint2 + 4 pad)
#define PA     68
#define SM_W1  0
#define SM_W2  (128 * PW1R)                  // 33792
#define SM_AS  (SM_W2 + 64 * PW2R)           // 42496
#define SM_B1  (SM_AS + GM * PA)             // 51200
#define SM_B2  (SM_B1 + CMID)
#define GF_WORDS (SM_B2 + COUT)              // 51392 words ~ 205.6KB
#define GF_SMEM_BYTES (GF_WORDS * 4)

__global__ __launch_bounds__(256, 1)
void gemm_fused(const float* __restrict__ x, const float* __restrict__ W1,
                const float* __restrict__ b1, const float* __restrict__ W2,
                const float* __restrict__ b2) {
    extern __shared__ uint32_t sm[];
    uint32_t* W1p = sm + SM_W1;              // 128 rows x 264 words
    uint32_t* W2p = sm + SM_W2;              // 64 rows x 136 words
    uint32_t* As  = sm + SM_AS;              // [128][68] tf32
    float*    b1s = (float*)(sm + SM_B1);    // [128]
    float*    b2s = (float*)(sm + SM_B2);    // [64]

    int tid = threadIdx.x, wid = tid >> 5, lane = tid & 31;
    int g = lane >> 2, t = lane & 3;
    int m0 = (wid & 3) * 32;        // rows (both GEMMs)
    int n1 = (wid >> 2) * 64;       // GEMM1 col block (also its mid half)
    int n2 = (wid >> 2) * 32;       // GEMM2 col block

    // ---- fused accumulator zeroing (grid-stride) ----
    {
        int gstride = gridDim.x * blockDim.x;
        float4 z = make_float4(0.f, 0.f, 0.f, 0.f);
        for (int i = blockIdx.x * blockDim.x + tid; i < NV * COUT / 4; i += gstride) {
            ((float4*)g_hgsum)[i] = z;
            ((float4*)g_gsum)[i]  = z;
            if (i < NE * COUT / 4) ((float4*)g_esum)[i] = z;
            if (i < NE)            g_ecnt[i] = 0.f;
            if (i < NV) { g_vcnt_hg[i] = 0.f; g_vcnt_g[i] = 0.f; }
        }
    }

    // ---- stage weights in paired layout ----
    for (int i = tid; i < CIN * CMID; i += 256) {
        int k = i >> 7, n = i & 127;
        int row = (k >> 3) * 4 + (k & 3);
        int e = (k >> 2) & 1;
        W1p[row * PW1R + n * 2 + e] = cvt_tf32(W1[i]);
    }
    for (int i = tid; i < CMID * COUT; i += 256) {
        int k = i >> 6, n = i & 63;
        int row = (k >> 3) * 4 + (k & 3);
        int e = (k >> 2) & 1;
        W2p[row * PW2R + n * 2 + e] = cvt_tf32(W2[i]);
    }
    if (tid < CMID) b1s[tid] = b1[tid];
    if (tid < COUT) b2s[tid] = b2[tid];

    int ntiles = (NV + GM - 1) / GM;   // 782
    for (int tile = blockIdx.x; tile < ntiles; tile += gridDim.x) {
        int row0 = tile * GM;

        // ---------------- GEMM1 ----------------
        float c1[2][8][4];
#pragma unroll
        for (int mt = 0; mt < 2; mt++)
#pragma unroll
            for (int nt = 0; nt < 8; nt++)
#pragma unroll
                for (int q = 0; q < 4; q++) c1[mt][nt][q] = 0.f;

        for (int kc = 0; kc < 4; kc++) {
            __syncthreads();
            for (int i = tid * 4; i < GM * 64; i += 256 * 4) {
                int r = i >> 6, kk = i & 63;
                int grow = row0 + r;
                float4 xv = (grow < NV)
                    ? *(const float4*)(x + (size_t)grow * CIN + kc * 64 + kk)
                    : make_float4(0.f, 0.f, 0.f, 0.f);
                uint4 tv;
                tv.x = cvt_tf32(xv.x); tv.y = cvt_tf32(xv.y);
                tv.z = cvt_tf32(xv.z); tv.w = cvt_tf32(xv.w);
                *(uint4*)(As + r * PA + kk) = tv;
            }
            __syncthreads();

#pragma unroll
            for (int s = 0; s < 8; s++) {
                int k0 = s * 8;
                int wrow = ((kc * 8 + s) * 4 + t) * PW1R;
                uint32_t a[2][4];
#pragma unroll
                for (int mt = 0; mt < 2; mt++) {
                    int r = m0 + mt * 16 + g;
                    a[mt][0] = As[r * PA + k0 + t];
                    a[mt][1] = As[(r + 8) * PA + k0 + t];
                    a[mt][2] = As[r * PA + k0 + t + 4];
                    a[mt][3] = As[(r + 8) * PA + k0 + t + 4];
                }
                uint32_t b[8][2];
#pragma unroll
                for (int nt = 0; nt < 8; nt++) {
                    int n = n1 + nt * 8 + g;
                    uint2 bv = *(const uint2*)(W1p + wrow + n * 2);
                    b[nt][0] = bv.x; b[nt][1] = bv.y;
                }
#pragma unroll
                for (int mt = 0; mt < 2; mt++)
#pragma unroll
                    for (int nt = 0; nt < 8; nt++)
                        mma_tf32(c1[mt][nt], a[mt], b[nt]);
            }
        }

        // ---------------- GEMM2 (two K-halves relayed through As) ----------
        float c2[2][4][4];
#pragma unroll
        for (int mt = 0; mt < 2; mt++)
#pragma unroll
            for (int nt = 0; nt < 4; nt++)
#pragma unroll
                for (int q = 0; q < 4; q++) c2[mt][nt][q] = 0.f;

#pragma unroll
        for (int half = 0; half < 2; half++) {
            __syncthreads();
            if ((wid >> 2) == half) {
#pragma unroll
                for (int mt = 0; mt < 2; mt++) {
                    int r = m0 + mt * 16 + g;
#pragma unroll
                    for (int nt = 0; nt < 8; nt++) {
                        int col = nt * 8 + 2 * t;           // 0..63 local
                        float bx = b1s[n1 + col], by = b1s[n1 + col + 1];
                        uint2 v0, v1;
                        v0.x = cvt_tf32(lrelu(c1[mt][nt][0] + bx));
                        v0.y = cvt_tf32(lrelu(c1[mt][nt][1] + by));
                        v1.x = cvt_tf32(lrelu(c1[mt][nt][2] + bx));
                        v1.y = cvt_tf32(lrelu(c1[mt][nt][3] + by));
                        *(uint2*)(As + r * PA + col) = v0;
                        *(uint2*)(As + (r + 8) * PA + col) = v1;
                    }
                }
            }
            __syncthreads();
#pragma unroll
            for (int s = 0; s < 8; s++) {
                int k0 = s * 8;                  // local k in this half
                int wrow = ((half * 8 + s) * 4 + t) * PW2R;
                uint32_t a[2][4];
#pragma unroll
                for (int mt = 0; mt < 2; mt++) {
                    int r = m0 + mt * 16 + g;
                    a[mt][0] = As[r * PA + k0 + t];
                    a[mt][1] = As[(r + 8) * PA + k0 + t];
                    a[mt][2] = As[r * PA + k0 + t + 4];
                    a[mt][3] = As[(r + 8) * PA + k0 + t + 4];
                }
                uint32_t b[4][2];
#pragma unroll
                for (int nt = 0; nt < 4; nt++) {
                    int n = n2 + nt * 8 + g;
                    uint2 bv = *(const uint2*)(W2p + wrow + n * 2);
                    b[nt][0] = bv.x; b[nt][1] = bv.y;
                }
#pragma unroll
                for (int mt = 0; mt < 2; mt++)
#pragma unroll
                    for (int nt = 0; nt < 4; nt++)
                        mma_tf32(c2[mt][nt], a[mt], b[nt]);
            }
        }

        // ---------------- epilogue: h -> g_h (f32) + g_hb (bf16) -----------
#pragma unroll
        for (int mt = 0; mt < 2; mt++) {
            int r0 = row0 + m0 + mt * 16 + g;
#pragma unroll
            for (int nt = 0; nt < 4; nt++) {
                int col = n2 + nt * 8 + 2 * t;
                float bx = b2s[col], by = b2s[col + 1];
                if (r0 < NV) {
                    float2 o; o.x = c2[mt][nt][0] + bx; o.y = c2[mt][nt][1] + by;
                    *(float2*)(g_h + (size_t)r0 * COUT + col) = o;
                    *(__nv_bfloat162*)(g_hb + (size_t)r0 * COUT + col) =
                        __floats2bfloat162_rn(o.x, o.y);
                }
                if (r0 + 8 < NV) {
                    float2 o; o.x = c2[mt][nt][2] + bx; o.y = c2[mt][nt][3] + by;
                    *(float2*)(g_h + (size_t)(r0 + 8) * COUT + col) = o;
                    *(__nv_bfloat162*)(g_hb + (size_t)(r0 + 8) * COUT + col) =
                        __floats2bfloat162_rn(o.x, o.y);
                }
            }
        }
    }
}

// ---------------- bf16-read scatter helper ----------------------------------
__device__ __forceinline__ void scat_bf16(const __nv_bfloat16* __restrict__ feat,
                                          int s, int d, int l,
                                          float* __restrict__ sum,
                                          float* __restrict__ cnt) {
    uint2 raw = *(const uint2*)(feat + (size_t)s * COUT + l * 4);
    float2 lo = __bfloat1622float2(*(__nv_bfloat162*)&raw.x);
    float2 hi = __bfloat1622float2(*(__nv_bfloat162*)&raw.y);
    float* dst = sum + (size_t)d * COUT + l * 4;
    asm volatile("red.global.add.v4.f32 [%0], {%1,%2,%3,%4};"
                 :: "l"(dst), "f"(lo.x), "f"(lo.y), "f"(hi.x), "f"(hi.y)
                 : "memory");
    if (l == 0) atomicAdd(cnt + d, 1.0f);
}

// ---------------- merged scatter: v2e + graph (both read g_hb) --------------
__global__ void scatter2_kernel(const int* __restrict__ hg_v,
                                const int* __restrict__ hg_e,
                                const int* __restrict__ g_srcp,
                                const int* __restrict__ g_dstp,
                                float* __restrict__ esum, float* __restrict__ ecnt,
                                float* __restrict__ gsum, float* __restrict__ gcnt) {
    long long tt = (long long)blockIdx.x * blockDim.x + threadIdx.x;
    const int half = NP * 16;
    const int* sidx; const int* didx; float* sum; float* cnt;
    int t;
    if (tt < half) {
        t = (int)tt;  sidx = hg_v;  didx = hg_e;  sum = esum; cnt = ecnt;
    } else {
        t = (int)(tt - half); sidx = g_srcp; didx = g_dstp; sum = gsum; cnt = gcnt;
    }
    int i = t >> 4;
    if (i >= NP) return;
    int l = t & 15;
    scat_bf16(g_hb, __ldg(sidx + i), __ldg(didx + i), l, sum, cnt);
}

// ---------------- e2v scatter (reads bf16 efeat) ----------------------------
__global__ void scatter_e2v_kernel(const int* __restrict__ hg_e,
                                   const int* __restrict__ hg_v,
                                   float* __restrict__ sum,
                                   float* __restrict__ cnt) {
    int t = blockIdx.x * blockDim.x + threadIdx.x;
    int i = t >> 4;
    if (i >= NP) return;
    int l = t & 15;
    scat_bf16(g_efb, __ldg(hg_e + i), __ldg(hg_v + i), l, sum, cnt);
}

// ---------------- e_feat(bf16) = e_sum / max(cnt,1) -------------------------
__global__ void efeat_kernel() {
    int i = blockIdx.x * blockDim.x + threadIdx.x;   // bf16x2 elements
    if (i >= NE * COUT / 2) return;
    float c = fmaxf(g_ecnt[i >> 5], 1.0f);
    float inv = 1.0f / c;
    float2 v = ((const float2*)g_esum)[i];
    ((__nv_bfloat162*)g_efb)[i] = __floats2bfloat162_rn(v.x * inv, v.y * inv);
}

// ---------------- final fuse + activation ----------------------------------
__global__ void final_kernel(const float* __restrict__ w, float* __restrict__ out) {
    int t = blockIdx.x * blockDim.x + threadIdx.x;
    if (t >= NV * COUT / 4) return;
    int v = t >> 4;
    float e0 = expf(w[0]), e1 = expf(w[1]);
    float sw0 = e0 / (e0 + e1), sw1 = e1 / (e0 + e1);
    float ih = 1.0f / fmaxf(g_vcnt_hg[v], 1.0f);
    float ig = 1.0f / fmaxf(g_vcnt_g[v], 1.0f);
    float4 hg = ((const float4*)g_hgsum)[t];
    float4 gg = ((const float4*)g_gsum)[t];
    float4 h  = ((const float4*)g_h)[t];
    float4 o;
    o.x = lrelu(sw0 * 0.5f * (gg.x * ig + hg.x * ih) + sw1 * h.x);
    o.y = lrelu(sw0 * 0.5f * (gg.y * ig + hg.y * ih) + sw1 * h.y);
    o.z = lrelu(sw0 * 0.5f * (gg.z * ig + hg.z * ih) + sw1 * h.z);
    o.w = lrelu(sw0 * 0.5f * (gg.w * ig + hg.w * ih) + sw1 * h.w);
    ((float4*)out)[t] = o;
}

// ---------------- launch ----------------------------------------------------
extern "C" void kernel_launch(void* const* d_in, const int* in_sizes, int n_in,
                              void* d_out, int out_size) {
    const float* x    = (const float*)d_in[0];
    const float* W1   = (const float*)d_in[1];
    const float* b1   = (const float*)d_in[2];
    const float* W2   = (const float*)d_in[3];
    const float* b2   = (const float*)d_in[4];
    const float* w    = (const float*)d_in[5];
    const int*   hg_v = (const int*)d_in[6];
    const int*   hg_e = (const int*)d_in[7];
    const int*   g_src= (const int*)d_in[8];
    const int*   g_dst= (const int*)d_in[9];
    float* out = (float*)d_out;

    float *p_esum, *p_ecnt, *p_hgsum, *p_gsum, *p_vch, *p_vcg;
    cudaGetSymbolAddress((void**)&p_esum,  g_esum);
    cudaGetSymbolAddress((void**)&p_ecnt,  g_ecnt);
    cudaGetSymbolAddress((void**)&p_hgsum, g_hgsum);
    cudaGetSymbolAddress((void**)&p_gsum,  g_gsum);
    cudaGetSymbolAddress((void**)&p_vch,   g_vcnt_hg);
    cudaGetSymbolAddress((void**)&p_vcg,   g_vcnt_g);

    cudaFuncSetAttribute(gemm_fused, cudaFuncAttributeMaxDynamicSharedMemorySize,
                         GF_SMEM_BYTES);

    gemm_fused<<<148, 256, GF_SMEM_BYTES>>>(x, W1, b1, W2, b2);

    // v2e + graph scatters in one launch (both read g_hb)
    long long tot = 2LL * NP * 16;
    scatter2_kernel<<<(int)((tot + 255) / 256), 256>>>(hg_v, hg_e, g_src, g_dst,
                                                       p_esum, p_ecnt, p_gsum, p_vcg);
    efeat_kernel<<<(NE * COUT / 2 + 255) / 256, 256>>>();
    scatter_e2v_kernel<<<(NP * 16 + 255) / 256, 256>>>(hg_e, hg_v, p_hgsum, p_vch);
    final_kernel<<<(NV * COUT / 4 + 255) / 256, 256>>>(w, out);
}

// round 14
// speedup vs baseline: 1.6116x; 1.0489x over previous
#include <cuda_runtime.h>
#include <cuda_bf16.h>
#include <math.h>
#include <cstdint>

#define NV   100000
#define NE   10000
#define NP   1600000
#define CIN  256
#define CMID 128
#define COUT 64
#define NEG  0.2f

// ---------------- scratch (device globals; no allocation allowed) ----------
__device__ float g_h[NV * COUT];        // MLP output h (f32, exact path)
__device__ __nv_bfloat16 g_hb[NV * COUT];   // bf16 shadow of h (scatter reads)
__device__ __nv_bfloat16 g_efb[NE * COUT];  // bf16 e_feat (scatter reads)
__device__ float g_esum[NE * COUT];     // hyperedge accumulator
__device__ float g_ecnt[NE];            // hyperedge degree
__device__ float g_hgsum[NV * COUT];    // e2v accumulator
__device__ float g_gsum[NV * COUT];     // graph accumulator
__device__ float g_vcnt_hg[NV];         // vertex incidence degree
__device__ float g_vcnt_g[NV];          // vertex graph in-degree

__device__ __forceinline__ float lrelu(float v) { return v > 0.f ? v : NEG * v; }

__device__ __forceinline__ uint32_t cvt_tf32(float f) {
    uint32_t u;
    asm("cvt.rna.tf32.f32 %0, %1;" : "=r"(u) : "f"(f));
    return u;
}
__device__ __forceinline__ void mma_tf32(float* c, const uint32_t* a,
                                         const uint32_t* b) {
    asm volatile(
        "mma.sync.aligned.m16n8k8.row.col.f32.tf32.tf32.f32 "
        "{%0,%1,%2,%3}, {%4,%5,%6,%7}, {%8,%9}, {%0,%1,%2,%3};"
        : "+f"(c[0]), "+f"(c[1]), "+f"(c[2]), "+f"(c[3])
        : "r"(a[0]), "r"(a[1]), "r"(a[2]), "r"(a[3]), "r"(b[0]), "r"(b[1]));
}

// ========== fused MLP (mma.sync tf32): h = lrelu(x@W1+b1)@W2 + b2 ==========
// Persistent 148 CTAs, 256 threads. Fragment-paired resident weights
// (conflict-free LDS.64 b-frags). A-staging is register-prefetch pipelined:
// next chunk's global loads issue during current chunk's MMA phase.
#define GM     128
#define PW1R   264          // W1p row stride in words (128 uint2 + 4 pad)
#define PW2R   136          // W2p row stride in words (64 uint2 + 4 pad)
#define PA     68
#define SM_W1  0
#define SM_W2  (128 * PW1R)                  // 33792
#define SM_AS  (SM_W2 + 64 * PW2R)           // 42496
#define SM_B1  (SM_AS + GM * PA)             // 51200
#define SM_B2  (SM_B1 + CMID)
#define GF_WORDS (SM_B2 + COUT)              // 51392 words ~ 205.6KB
#define GF_SMEM_BYTES (GF_WORDS * 4)

__global__ __launch_bounds__(256, 1)
void gemm_fused(const float* __restrict__ x, const float* __restrict__ W1,
                const float* __restrict__ b1, const float* __restrict__ W2,
                const float* __restrict__ b2) {
    extern __shared__ uint32_t sm[];
    uint32_t* W1p = sm + SM_W1;              // 128 rows x 264 words
    uint32_t* W2p = sm + SM_W2;              // 64 rows x 136 words
    uint32_t* As  = sm + SM_AS;              // [128][68] tf32
    float*    b1s = (float*)(sm + SM_B1);    // [128]
    float*    b2s = (float*)(sm + SM_B2);    // [64]

    int tid = threadIdx.x, wid = tid >> 5, lane = tid & 31;
    int g = lane >> 2, t = lane & 3;
    int m0 = (wid & 3) * 32;        // rows (both GEMMs)
    int n1 = (wid >> 2) * 64;       // GEMM1 col block (also its mid half)
    int n2 = (wid >> 2) * 32;       // GEMM2 col block

    // ---- fused accumulator zeroing (grid-stride) ----
    {
        int gstride = gridDim.x * blockDim.x;
        float4 z = make_float4(0.f, 0.f, 0.f, 0.f);
        for (int i = blockIdx.x * blockDim.x + tid; i < NV * COUT / 4; i += gstride) {
            ((float4*)g_hgsum)[i] = z;
            ((float4*)g_gsum)[i]  = z;
            if (i < NE * COUT / 4) ((float4*)g_esum)[i] = z;
            if (i < NE)            g_ecnt[i] = 0.f;
            if (i < NV) { g_vcnt_hg[i] = 0.f; g_vcnt_g[i] = 0.f; }
        }
    }

    // ---- stage weights in paired layout ----
    for (int i = tid; i < CIN * CMID; i += 256) {
        int k = i >> 7, n = i & 127;
        int row = (k >> 3) * 4 + (k & 3);
        int e = (k >> 2) & 1;
        W1p[row * PW1R + n * 2 + e] = cvt_tf32(W1[i]);
    }
    for (int i = tid; i < CMID * COUT; i += 256) {
        int k = i >> 6, n = i & 63;
        int row = (k >> 3) * 4 + (k & 3);
        int e = (k >> 2) & 1;
        W2p[row * PW2R + n * 2 + e] = cvt_tf32(W2[i]);
    }
    if (tid < CMID) b1s[tid] = b1[tid];
    if (tid < COUT) b2s[tid] = b2[tid];

    // per-thread A-staging map: 8 x float4 per chunk (GM*64 floats / 256 thr)
    // i = (tid*4 + p*1024), row = i>>6, kk = i&63
    int ntiles = (NV + GM - 1) / GM;   // 782
    for (int tile = blockIdx.x; tile < ntiles; tile += gridDim.x) {
        int row0 = tile * GM;

        // ---------------- GEMM1 (register-prefetch pipelined staging) ------
        float c1[2][8][4];
#pragma unroll
        for (int mt = 0; mt < 2; mt++)
#pragma unroll
            for (int nt = 0; nt < 8; nt++)
#pragma unroll
                for (int q = 0; q < 4; q++) c1[mt][nt][q] = 0.f;

        float4 pre[8];
        // preload chunk 0
#pragma unroll
        for (int p = 0; p < 8; p++) {
            int i = tid * 4 + p * 1024;
            int r = i >> 6, kk = i & 63;
            int grow = row0 + r;
            pre[p] = (grow < NV)
                ? *(const float4*)(x + (size_t)grow * CIN + kk)
                : make_float4(0.f, 0.f, 0.f, 0.f);
        }

        for (int kc = 0; kc < 4; kc++) {
            __syncthreads();   // As free (previous consumers done)
#pragma unroll
            for (int p = 0; p < 8; p++) {
                int i = tid * 4 + p * 1024;
                int r = i >> 6, kk = i & 63;
                uint4 tv;
                tv.x = cvt_tf32(pre[p].x); tv.y = cvt_tf32(pre[p].y);
                tv.z = cvt_tf32(pre[p].z); tv.w = cvt_tf32(pre[p].w);
                *(uint4*)(As + r * PA + kk) = tv;
            }
            __syncthreads();   // As ready
            if (kc < 3) {
                // prefetch next chunk while MMAs below execute
#pragma unroll
                for (int p = 0; p < 8; p++) {
                    int i = tid * 4 + p * 1024;
                    int r = i >> 6, kk = i & 63;
                    int grow = row0 + r;
                    pre[p] = (grow < NV)
                        ? *(const float4*)(x + (size_t)grow * CIN + (kc + 1) * 64 + kk)
                        : make_float4(0.f, 0.f, 0.f, 0.f);
                }
            }

#pragma unroll
            for (int s = 0; s < 8; s++) {
                int k0 = s * 8;
                int wrow = ((kc * 8 + s) * 4 + t) * PW1R;
                uint32_t a[2][4];
#pragma unroll
                for (int mt = 0; mt < 2; mt++) {
                    int r = m0 + mt * 16 + g;
                    a[mt][0] = As[r * PA + k0 + t];
                    a[mt][1] = As[(r + 8) * PA + k0 + t];
                    a[mt][2] = As[r * PA + k0 + t + 4];
                    a[mt][3] = As[(r + 8) * PA + k0 + t + 4];
                }
                uint32_t b[8][2];
#pragma unroll
                for (int nt = 0; nt < 8; nt++) {
                    int n = n1 + nt * 8 + g;
                    uint2 bv = *(const uint2*)(W1p + wrow + n * 2);
                    b[nt][0] = bv.x; b[nt][1] = bv.y;
                }
#pragma unroll
                for (int mt = 0; mt < 2; mt++)
#pragma unroll
                    for (int nt = 0; nt < 8; nt++)
                        mma_tf32(c1[mt][nt], a[mt], b[nt]);
            }
        }

        // ---------------- GEMM2 (two K-halves relayed through As) ----------
        float c2[2][4][4];
#pragma unroll
        for (int mt = 0; mt < 2; mt++)
#pragma unroll
            for (int nt = 0; nt < 4; nt++)
#pragma unroll
                for (int q = 0; q < 4; q++) c2[mt][nt][q] = 0.f;

#pragma unroll
        for (int half = 0; half < 2; half++) {
            __syncthreads();
            if ((wid >> 2) == half) {
#pragma unroll
                for (int mt = 0; mt < 2; mt++) {
                    int r = m0 + mt * 16 + g;
#pragma unroll
                    for (int nt = 0; nt < 8; nt++) {
                        int col = nt * 8 + 2 * t;           // 0..63 local
                        float bx = b1s[n1 + col], by = b1s[n1 + col + 1];
                        uint2 v0, v1;
                        v0.x = cvt_tf32(lrelu(c1[mt][nt][0] + bx));
                        v0.y = cvt_tf32(lrelu(c1[mt][nt][1] + by));
                        v1.x = cvt_tf32(lrelu(c1[mt][nt][2] + bx));
                        v1.y = cvt_tf32(lrelu(c1[mt][nt][3] + by));
                        *(uint2*)(As + r * PA + col) = v0;
                        *(uint2*)(As + (r + 8) * PA + col) = v1;
                    }
                }
            }
            __syncthreads();
#pragma unroll
            for (int s = 0; s < 8; s++) {
                int k0 = s * 8;                  // local k in this half
                int wrow = ((half * 8 + s) * 4 + t) * PW2R;
                uint32_t a[2][4];
#pragma unroll
                for (int mt = 0; mt < 2; mt++) {
                    int r = m0 + mt * 16 + g;
                    a[mt][0] = As[r * PA + k0 + t];
                    a[mt][1] = As[(r + 8) * PA + k0 + t];
                    a[mt][2] = As[r * PA + k0 + t + 4];
                    a[mt][3] = As[(r + 8) * PA + k0 + t + 4];
                }
                uint32_t b[4][2];
#pragma unroll
                for (int nt = 0; nt < 4; nt++) {
                    int n = n2 + nt * 8 + g;
                    uint2 bv = *(const uint2*)(W2p + wrow + n * 2);
                    b[nt][0] = bv.x; b[nt][1] = bv.y;
                }
#pragma unroll
                for (int mt = 0; mt < 2; mt++)
#pragma unroll
                    for (int nt = 0; nt < 4; nt++)
                        mma_tf32(c2[mt][nt], a[mt], b[nt]);
            }
        }

        // ---------------- epilogue: h -> g_h (f32) + g_hb (bf16) -----------
#pragma unroll
        for (int mt = 0; mt < 2; mt++) {
            int r0 = row0 + m0 + mt * 16 + g;
#pragma unroll
            for (int nt = 0; nt < 4; nt++) {
                int col = n2 + nt * 8 + 2 * t;
                float bx = b2s[col], by = b2s[col + 1];
                if (r0 < NV) {
                    float2 o; o.x = c2[mt][nt][0] + bx; o.y = c2[mt][nt][1] + by;
                    *(float2*)(g_h + (size_t)r0 * COUT + col) = o;
                    *(__nv_bfloat162*)(g_hb + (size_t)r0 * COUT + col) =
                        __floats2bfloat162_rn(o.x, o.y);
                }
                if (r0 + 8 < NV) {
                    float2 o; o.x = c2[mt][nt][2] + bx; o.y = c2[mt][nt][3] + by;
                    *(float2*)(g_h + (size_t)(r0 + 8) * COUT + col) = o;
                    *(__nv_bfloat162*)(g_hb + (size_t)(r0 + 8) * COUT + col) =
                        __floats2bfloat162_rn(o.x, o.y);
                }
            }
        }
    }
}

// ---------------- bf16-read scatter helper ----------------------------------
__device__ __forceinline__ void scat_bf16(const __nv_bfloat16* __restrict__ feat,
                                          int s, int d, int l,
                                          float* __restrict__ sum,
                                          float* __restrict__ cnt) {
    uint2 raw = *(const uint2*)(feat + (size_t)s * COUT + l * 4);
    float2 lo = __bfloat1622float2(*(__nv_bfloat162*)&raw.x);
    float2 hi = __bfloat1622float2(*(__nv_bfloat162*)&raw.y);
    float* dst = sum + (size_t)d * COUT + l * 4;
    asm volatile("red.global.add.v4.f32 [%0], {%1,%2,%3,%4};"
                 :: "l"(dst), "f"(lo.x), "f"(lo.y), "f"(hi.x), "f"(hi.y)
                 : "memory");
    if (l == 0) atomicAdd(cnt + d, 1.0f);
}

// ---------------- merged scatter: v2e + graph (2D grid, y = pass) ----------
__global__ void scatter2_kernel(const int* __restrict__ hg_v,
                                const int* __restrict__ hg_e,
                                const int* __restrict__ g_srcp,
                                const int* __restrict__ g_dstp,
                                float* __restrict__ esum, float* __restrict__ ecnt,
                                float* __restrict__ gsum, float* __restrict__ gcnt) {
    int t = blockIdx.x * blockDim.x + threadIdx.x;
    int i = t >> 4;
    if (i >= NP) return;
    int l = t & 15;
    if (blockIdx.y == 0)
        scat_bf16(g_hb, __ldg(hg_v + i), __ldg(hg_e + i), l, esum, ecnt);
    else
        scat_bf16(g_hb, __ldg(g_srcp + i), __ldg(g_dstp + i), l, gsum, gcnt);
}

// ---------------- e2v scatter (reads bf16 efeat) ----------------------------
__global__ void scatter_e2v_kernel(const int* __restrict__ hg_e,
                                   const int* __restrict__ hg_v,
                                   float* __restrict__ sum,
                                   float* __restrict__ cnt) {
    int t = blockIdx.x * blockDim.x + threadIdx.x;
    int i = t >> 4;
    if (i >= NP) return;
    int l = t & 15;
    scat_bf16(g_efb, __ldg(hg_e + i), __ldg(hg_v + i), l, sum, cnt);
}

// ---------------- e_feat(bf16) = e_sum / max(cnt,1) -------------------------
__global__ void efeat_kernel() {
    int i = blockIdx.x * blockDim.x + threadIdx.x;   // bf16x2 elements
    if (i >= NE * COUT / 2) return;
    float c = fmaxf(g_ecnt[i >> 5], 1.0f);
    float inv = 1.0f / c;
    float2 v = ((const float2*)g_esum)[i];
    ((__nv_bfloat162*)g_efb)[i] = __floats2bfloat162_rn(v.x * inv, v.y * inv);
}

// ---------------- final fuse + activation ----------------------------------
__global__ void final_kernel(const float* __restrict__ w, float* __restrict__ out) {
    int t = blockIdx.x * blockDim.x + threadIdx.x;
    if (t >= NV * COUT / 4) return;
    int v = t >> 4;
    float e0 = expf(w[0]), e1 = expf(w[1]);
    float sw0 = e0 / (e0 + e1), sw1 = e1 / (e0 + e1);
    float ih = 1.0f / fmaxf(g_vcnt_hg[v], 1.0f);
    float ig = 1.0f / fmaxf(g_vcnt_g[v], 1.0f);
    float4 hg = ((const float4*)g_hgsum)[t];
    float4 gg = ((const float4*)g_gsum)[t];
    float4 h  = ((const float4*)g_h)[t];
    float4 o;
    o.x = lrelu(sw0 * 0.5f * (gg.x * ig + hg.x * ih) + sw1 * h.x);
    o.y = lrelu(sw0 * 0.5f * (gg.y * ig + hg.y * ih) + sw1 * h.y);
    o.z = lrelu(sw0 * 0.5f * (gg.z * ig + hg.z * ih) + sw1 * h.z);
    o.w = lrelu(sw0 * 0.5f * (gg.w * ig + hg.w * ih) + sw1 * h.w);
    ((float4*)out)[t] = o;
}

// ---------------- launch ----------------------------------------------------
extern "C" void kernel_launch(void* const* d_in, const int* in_sizes, int n_in,
                              void* d_out, int out_size) {
    const float* x    = (const float*)d_in[0];
    const float* W1   = (const float*)d_in[1];
    const float* b1   = (const float*)d_in[2];
    const float* W2   = (const float*)d_in[3];
    const float* b2   = (const float*)d_in[4];
    const float* w    = (const float*)d_in[5];
    const int*   hg_v = (const int*)d_in[6];
    const int*   hg_e = (const int*)d_in[7];
    const int*   g_src= (const int*)d_in[8];
    const int*   g_dst= (const int*)d_in[9];
    float* out = (float*)d_out;

    float *p_esum, *p_ecnt, *p_hgsum, *p_gsum, *p_vch, *p_vcg;
    cudaGetSymbolAddress((void**)&p_esum,  g_esum);
    cudaGetSymbolAddress((void**)&p_ecnt,  g_ecnt);
    cudaGetSymbolAddress((void**)&p_hgsum, g_hgsum);
    cudaGetSymbolAddress((void**)&p_gsum,  g_gsum);
    cudaGetSymbolAddress((void**)&p_vch,   g_vcnt_hg);
    cudaGetSymbolAddress((void**)&p_vcg,   g_vcnt_g);

    cudaFuncSetAttribute(gemm_fused, cudaFuncAttributeMaxDynamicSharedMemorySize,
                         GF_SMEM_BYTES);

    gemm_fused<<<148, 256, GF_SMEM_BYTES>>>(x, W1, b1, W2, b2);

    // v2e + graph scatters in one launch (2D grid: y=0 v2e, y=1 graph)
    dim3 sgrid((NP * 16 + 255) / 256, 2);
    scatter2_kernel<<<sgrid, 256>>>(hg_v, hg_e, g_src, g_dst,
                                    p_esum, p_ecnt, p_gsum, p_vcg);
    efeat_kernel<<<(NE * COUT / 2 + 255) / 256, 256>>>();
    scatter_e2v_kernel<<<(NP * 16 + 255) / 256, 256>>>(hg_e, hg_v, p_hgsum, p_vch);
    final_kernel<<<(NV * COUT / 4 + 255) / 256, 256>>>(w, out);
}

// round 15
// speedup vs baseline: 1.6642x; 1.0327x over previous
#include <cuda_runtime.h>
#include <cuda_bf16.h>
#include <math.h>
#include <cstdint>

#define NV   100000
#define NE   10000
#define NP   1600000
#define CIN  256
#define CMID 128
#define COUT 64
#define NEG  0.2f

// ---------------- scratch (device globals; no allocation allowed) ----------
__device__ float g_h[NV * COUT];        // MLP output h (f32, exact path)
__device__ __nv_bfloat16 g_hb[NV * COUT];   // bf16 shadow of h (scatter reads)
__device__ __nv_bfloat16 g_efb[NE * COUT];  // bf16 e_feat (scatter reads)
__device__ float g_esum[NE * COUT];     // hyperedge accumulator
__device__ float g_ecnt[NE];            // hyperedge degree
__device__ float g_hgsum[NV * COUT];    // e2v accumulator
__device__ float g_gsum[NV * COUT];     // graph accumulator
__device__ float g_vcnt_hg[NV];         // vertex incidence degree
__device__ float g_vcnt_g[NV];          // vertex graph in-degree

__device__ __forceinline__ float lrelu(float v) { return v > 0.f ? v : NEG * v; }

__device__ __forceinline__ uint32_t cvt_tf32(float f) {
    uint32_t u;
    asm("cvt.rna.tf32.f32 %0, %1;" : "=r"(u) : "f"(f));
    return u;
}
__device__ __forceinline__ void mma_tf32(float* c, const uint32_t* a,
                                         const uint32_t* b) {
    asm volatile(
        "mma.sync.aligned.m16n8k8.row.col.f32.tf32.tf32.f32 "
        "{%0,%1,%2,%3}, {%4,%5,%6,%7}, {%8,%9}, {%0,%1,%2,%3};"
        : "+f"(c[0]), "+f"(c[1]), "+f"(c[2]), "+f"(c[3])
        : "r"(a[0]), "r"(a[1]), "r"(a[2]), "r"(a[3]), "r"(b[0]), "r"(b[1]));
}

// ========== fused MLP (mma.sync tf32): h = lrelu(x@W1+b1)@W2 + b2 ==========
// Persistent 148 CTAs, 256 threads. GM=192 rows/tile (3 m-tiles/warp: B-frag
// LDS amortized over 1.5x rows). A staged in 8 chunks of 32 k-cols through
// TWO 192x36 buffers (double-buffered, register-prefetch, 1 sync/chunk).
// GEMM2 relays mid through the same buffers in 4 quarter-phases.
#define GM     192
#define PW1R   264          // W1p row stride (words)
#define PW2R   136          // W2p row stride (words)
#define PA     36           // A-chunk row stride (words), bank 4g+t clean
#define SM_W1  0
#define SM_W2  (128 * PW1R)                  // 33792
#define SM_A0  (SM_W2 + 64 * PW2R)           // 42496
#define SM_A1  (SM_A0 + GM * PA)             // 49408
#define SM_B1  (SM_A1 + GM * PA)             // 56320
#define SM_B2  (SM_B1 + CMID)                // 56448
#define GF_WORDS (SM_B2 + COUT)              // 56512 words = 226048 B
#define GF_SMEM_BYTES (GF_WORDS * 4)

__global__ __launch_bounds__(256, 1)
void gemm_fused(const float* __restrict__ x, const float* __restrict__ W1,
                const float* __restrict__ b1, const float* __restrict__ W2,
                const float* __restrict__ b2) {
    extern __shared__ uint32_t sm[];
    uint32_t* W1p = sm + SM_W1;
    uint32_t* W2p = sm + SM_W2;
    float*    b1s = (float*)(sm + SM_B1);
    float*    b2s = (float*)(sm + SM_B2);

    int tid = threadIdx.x, wid = tid >> 5, lane = tid & 31;
    int g = lane >> 2, t = lane & 3;
    int m0 = (wid & 3) * 48;        // warp row block (3 m16-tiles, x2 rows)
    int n1 = (wid >> 2) * 64;       // GEMM1 col block / mid half
    int n2 = (wid >> 2) * 32;       // GEMM2 col block

    // ---- fused accumulator zeroing (grid-stride) ----
    {
        int gstride = gridDim.x * blockDim.x;
        float4 z = make_float4(0.f, 0.f, 0.f, 0.f);
        for (int i = blockIdx.x * blockDim.x + tid; i < NV * COUT / 4; i += gstride) {
            ((float4*)g_hgsum)[i] = z;
            ((float4*)g_gsum)[i]  = z;
            if (i < NE * COUT / 4) ((float4*)g_esum)[i] = z;
            if (i < NE)            g_ecnt[i] = 0.f;
            if (i < NV) { g_vcnt_hg[i] = 0.f; g_vcnt_g[i] = 0.f; }
        }
    }

    // ---- stage weights in fragment-paired layout ----
    for (int i = tid; i < CIN * CMID; i += 256) {
        int k = i >> 7, n = i & 127;
        int row = (k >> 3) * 4 + (k & 3);
        int e = (k >> 2) & 1;
        W1p[row * PW1R + n * 2 + e] = cvt_tf32(W1[i]);
    }
    for (int i = tid; i < CMID * COUT; i += 256) {
        int k = i >> 6, n = i & 63;
        int row = (k >> 3) * 4 + (k & 3);
        int e = (k >> 2) & 1;
        W2p[row * PW2R + n * 2 + e] = cvt_tf32(W2[i]);
    }
    if (tid < CMID) b1s[tid] = b1[tid];
    if (tid < COUT) b2s[tid] = b2[tid];

    // per-thread A map: 6 float4/chunk; idx = tid*4 + p*1024; r=idx>>5 kk=idx&31
    int ntiles = (NV + GM - 1) / GM;   // 521
    for (int tile = blockIdx.x; tile < ntiles; tile += gridDim.x) {
        int row0 = tile * GM;

        float c1[3][8][4];
#pragma unroll
        for (int mt = 0; mt < 3; mt++)
#pragma unroll
            for (int nt = 0; nt < 8; nt++)
#pragma unroll
                for (int q = 0; q < 4; q++) c1[mt][nt][q] = 0.f;

        float4 pre[6];
#pragma unroll
        for (int p = 0; p < 6; p++) {
            int i = tid * 4 + p * 1024;
            int r = i >> 5, kk = i & 31;
            int grow = row0 + r;
            pre[p] = (grow < NV)
                ? *(const float4*)(x + (size_t)grow * CIN + kk)
                : make_float4(0.f, 0.f, 0.f, 0.f);
        }
        __syncthreads();   // buffers free from previous tile

        for (int kc = 0; kc < 8; kc++) {
            uint32_t* buf = sm + ((kc & 1) ? SM_A1 : SM_A0);
#pragma unroll
            for (int p = 0; p < 6; p++) {
                int i = tid * 4 + p * 1024;
                int r = i >> 5, kk = i & 31;
                uint4 tv;
                tv.x = cvt_tf32(pre[p].x); tv.y = cvt_tf32(pre[p].y);
                tv.z = cvt_tf32(pre[p].z); tv.w = cvt_tf32(pre[p].w);
                *(uint4*)(buf + r * PA + kk) = tv;
            }
            if (kc < 7) {
#pragma unroll
                for (int p = 0; p < 6; p++) {
                    int i = tid * 4 + p * 1024;
                    int r = i >> 5, kk = i & 31;
                    int grow = row0 + r;
                    pre[p] = (grow < NV)
                        ? *(const float4*)(x + (size_t)grow * CIN + (kc + 1) * 32 + kk)
                        : make_float4(0.f, 0.f, 0.f, 0.f);
                }
            }
            __syncthreads();   // chunk kc visible to all

#pragma unroll
            for (int s = 0; s < 4; s++) {
                int k0 = s * 8;
                int wrow = ((kc * 4 + s) * 4 + t) * PW1R;
                uint32_t a[3][4];
#pragma unroll
                for (int mt = 0; mt < 3; mt++) {
                    int r = m0 + mt * 16 + g;
                    a[mt][0] = buf[r * PA + k0 + t];
                    a[mt][1] = buf[(r + 8) * PA + k0 + t];
                    a[mt][2] = buf[r * PA + k0 + t + 4];
                    a[mt][3] = buf[(r + 8) * PA + k0 + t + 4];
                }
                uint32_t b[8][2];
#pragma unroll
                for (int nt = 0; nt < 8; nt++) {
                    int n = n1 + nt * 8 + g;
                    uint2 bv = *(const uint2*)(W1p + wrow + n * 2);
                    b[nt][0] = bv.x; b[nt][1] = bv.y;
                }
#pragma unroll
                for (int mt = 0; mt < 3; mt++)
#pragma unroll
                    for (int nt = 0; nt < 8; nt++)
                        mma_tf32(c1[mt][nt], a[mt], b[nt]);
            }
        }

        // ---------------- GEMM2: 4 quarter relays through the buffers ------
        float c2[3][4][4];
#pragma unroll
        for (int mt = 0; mt < 3; mt++)
#pragma unroll
            for (int nt = 0; nt < 4; nt++)
#pragma unroll
                for (int q = 0; q < 4; q++) c2[mt][nt][q] = 0.f;

#pragma unroll
        for (int q = 0; q < 4; q++) {
            uint32_t* buf = sm + ((q & 1) ? SM_A1 : SM_A0);
            if ((wid >> 2) == (q >> 1)) {
                int nt0 = (q & 1) * 4;
#pragma unroll
                for (int mt = 0; mt < 3; mt++) {
                    int r = m0 + mt * 16 + g;
#pragma unroll
                    for (int nt = nt0; nt < nt0 + 4; nt++) {
                        int colg = nt * 8 + 2 * t;          // 0..63 within half
                        int lc   = colg - (q & 1) * 32;     // 0..31 in quarter
                        float bx = b1s[n1 + colg], by = b1s[n1 + colg + 1];
                        uint2 v0, v1;
                        v0.x = cvt_tf32(lrelu(c1[mt][nt][0] + bx));
                        v0.y = cvt_tf32(lrelu(c1[mt][nt][1] + by));
                        v1.x = cvt_tf32(lrelu(c1[mt][nt][2] + bx));
                        v1.y = cvt_tf32(lrelu(c1[mt][nt][3] + by));
                        *(uint2*)(buf + r * PA + lc) = v0;
                        *(uint2*)(buf + (r + 8) * PA + lc) = v1;
                    }
                }
            }
            __syncthreads();
#pragma unroll
            for (int s = 0; s < 4; s++) {
                int k0 = s * 8;
                int wrow = ((q * 4 + s) * 4 + t) * PW2R;
                uint32_t a[3][4];
#pragma unroll
                for (int mt = 0; mt < 3; mt++) {
                    int r = m0 + mt * 16 + g;
                    a[mt][0] = buf[r * PA + k0 + t];
                    a[mt][1] = buf[(r + 8) * PA + k0 + t];
                    a[mt][2] = buf[r * PA + k0 + t + 4];
                    a[mt][3] = buf[(r + 8) * PA + k0 + t + 4];
                }
                uint32_t b[4][2];
#pragma unroll
                for (int nt = 0; nt < 4; nt++) {
                    int n = n2 + nt * 8 + g;
                    uint2 bv = *(const uint2*)(W2p + wrow + n * 2);
                    b[nt][0] = bv.x; b[nt][1] = bv.y;
                }
#pragma unroll
                for (int mt = 0; mt < 3; mt++)
#pragma unroll
                    for (int nt = 0; nt < 4; nt++)
                        mma_tf32(c2[mt][nt], a[mt], b[nt]);
            }
        }

        // ---------------- epilogue: h -> g_h (f32) + g_hb (bf16) -----------
#pragma unroll
        for (int mt = 0; mt < 3; mt++) {
            int r0 = row0 + m0 + mt * 16 + g;
#pragma unroll
            for (int nt = 0; nt < 4; nt++) {
                int col = n2 + nt * 8 + 2 * t;
                float bx = b2s[col], by = b2s[col + 1];
                if (r0 < NV) {
                    float2 o; o.x = c2[mt][nt][0] + bx; o.y = c2[mt][nt][1] + by;
                    *(float2*)(g_h + (size_t)r0 * COUT + col) = o;
                    *(__nv_bfloat162*)(g_hb + (size_t)r0 * COUT + col) =
                        __floats2bfloat162_rn(o.x, o.y);
                }
                if (r0 + 8 < NV) {
                    float2 o; o.x = c2[mt][nt][2] + bx; o.y = c2[mt][nt][3] + by;
                    *(float2*)(g_h + (size_t)(r0 + 8) * COUT + col) = o;
                    *(__nv_bfloat162*)(g_hb + (size_t)(r0 + 8) * COUT + col) =
                        __floats2bfloat162_rn(o.x, o.y);
                }
            }
        }
    }
}

// ---------------- bf16-read scatter helper ----------------------------------
__device__ __forceinline__ void scat_bf16(const __nv_bfloat16* __restrict__ feat,
                                          int s, int d, int l,
                                          float* __restrict__ sum,
                                          float* __restrict__ cnt) {
    uint2 raw = *(const uint2*)(feat + (size_t)s * COUT + l * 4);
    float2 lo = __bfloat1622float2(*(__nv_bfloat162*)&raw.x);
    float2 hi = __bfloat1622float2(*(__nv_bfloat162*)&raw.y);
    float* dst = sum + (size_t)d * COUT + l * 4;
    asm volatile("red.global.add.v4.f32 [%0], {%1,%2,%3,%4};"
                 :: "l"(dst), "f"(lo.x), "f"(lo.y), "f"(hi.x), "f"(hi.y)
                 : "memory");
    if (l == 0) atomicAdd(cnt + d, 1.0f);
}

// ---------------- merged scatter: v2e + graph (2D grid, y = pass) ----------
__global__ void scatter2_kernel(const int* __restrict__ hg_v,
                                const int* __restrict__ hg_e,
                                const int* __restrict__ g_srcp,
                                const int* __restrict__ g_dstp,
                                float* __restrict__ esum, float* __restrict__ ecnt,
                                float* __restrict__ gsum, float* __restrict__ gcnt) {
    int t = blockIdx.x * blockDim.x + threadIdx.x;
    int i = t >> 4;
    if (i >= NP) return;
    int l = t & 15;
    if (blockIdx.y == 0)
        scat_bf16(g_hb, __ldg(hg_v + i), __ldg(hg_e + i), l, esum, ecnt);
    else
        scat_bf16(g_hb, __ldg(g_srcp + i), __ldg(g_dstp + i), l, gsum, gcnt);
}

// ---------------- e2v scatter (reads bf16 efeat) ----------------------------
__global__ void scatter_e2v_kernel(const int* __restrict__ hg_e,
                                   const int* __restrict__ hg_v,
                                   float* __restrict__ sum,
                                   float* __restrict__ cnt) {
    int t = blockIdx.x * blockDim.x + threadIdx.x;
    int i = t >> 4;
    if (i >= NP) return;
    int l = t & 15;
    scat_bf16(g_efb, __ldg(hg_e + i), __ldg(hg_v + i), l, sum, cnt);
}

// ---------------- e_feat(bf16) = e_sum / max(cnt,1) -------------------------
__global__ void efeat_kernel() {
    int i = blockIdx.x * blockDim.x + threadIdx.x;   // bf16x2 elements
    if (i >= NE * COUT / 2) return;
    float c = fmaxf(g_ecnt[i >> 5], 1.0f);
    float inv = 1.0f / c;
    float2 v = ((const float2*)g_esum)[i];
    ((__nv_bfloat162*)g_efb)[i] = __floats2bfloat162_rn(v.x * inv, v.y * inv);
}

// ---------------- final fuse + activation ----------------------------------
__global__ void final_kernel(const float* __restrict__ w, float* __restrict__ out) {
    int t = blockIdx.x * blockDim.x + threadIdx.x;
    if (t >= NV * COUT / 4) return;
    int v = t >> 4;
    float e0 = expf(w[0]), e1 = expf(w[1]);
    float sw0 = e0 / (e0 + e1), sw1 = e1 / (e0 + e1);
    float ih = 1.0f / fmaxf(g_vcnt_hg[v], 1.0f);
    float ig = 1.0f / fmaxf(g_vcnt_g[v], 1.0f);
    float4 hg = ((const float4*)g_hgsum)[t];
    float4 gg = ((const float4*)g_gsum)[t];
    float4 h  = ((const float4*)g_h)[t];
    float4 o;
    o.x = lrelu(sw0 * 0.5f * (gg.x * ig + hg.x * ih) + sw1 * h.x);
    o.y = lrelu(sw0 * 0.5f * (gg.y * ig + hg.y * ih) + sw1 * h.y);
    o.z = lrelu(sw0 * 0.5f * (gg.z * ig + hg.z * ih) + sw1 * h.z);
    o.w = lrelu(sw0 * 0.5f * (gg.w * ig + hg.w * ih) + sw1 * h.w);
    ((float4*)out)[t] = o;
}

// ---------------- launch ----------------------------------------------------
extern "C" void kernel_launch(void* const* d_in, const int* in_sizes, int n_in,
                              void* d_out, int out_size) {
    const float* x    = (const float*)d_in[0];
    const float* W1   = (const float*)d_in[1];
    const float* b1   = (const float*)d_in[2];
    const float* W2   = (const float*)d_in[3];
    const float* b2   = (const float*)d_in[4];
    const float* w    = (const float*)d_in[5];
    const int*   hg_v = (const int*)d_in[6];
    const int*   hg_e = (const int*)d_in[7];
    const int*   g_src= (const int*)d_in[8];
    const int*   g_dst= (const int*)d_in[9];
    float* out = (float*)d_out;

    float *p_esum, *p_ecnt, *p_hgsum, *p_gsum, *p_vch, *p_vcg;
    cudaGetSymbolAddress((void**)&p_esum,  g_esum);
    cudaGetSymbolAddress((void**)&p_ecnt,  g_ecnt);
    cudaGetSymbolAddress((void**)&p_hgsum, g_hgsum);
    cudaGetSymbolAddress((void**)&p_gsum,  g_gsum);
    cudaGetSymbolAddress((void**)&p_vch,   g_vcnt_hg);
    cudaGetSymbolAddress((void**)&p_vcg,   g_vcnt_g);

    cudaFuncSetAttribute(gemm_fused, cudaFuncAttributeMaxDynamicSharedMemorySize,
                         GF_SMEM_BYTES);

    gemm_fused<<<148, 256, GF_SMEM_BYTES>>>(x, W1, b1, W2, b2);

    // v2e + graph scatters in one launch (2D grid: y=0 v2e, y=1 graph)
    dim3 sgrid((NP * 16 + 255) / 256, 2);
    scatter2_kernel<<<sgrid, 256>>>(hg_v, hg_e, g_src, g_dst,
                                    p_esum, p_ecnt, p_gsum, p_vcg);
    efeat_kernel<<<(NE * COUT / 2 + 255) / 256, 256>>>();
    scatter_e2v_kernel<<<(NP * 16 + 255) / 256, 256>>>(hg_e, hg_v, p_hgsum, p_vch);
    final_kernel<<<(NV * COUT / 4 + 255) / 256, 256>>>(w, out);
}